// round 6
// baseline (speedup 1.0000x reference)
#include <cuda_runtime.h>
#include <cuda_bf16.h>
#include <cstdint>
#include <cstddef>

// ---------------------------------------------------------------------------
// Problem constants
// ---------------------------------------------------------------------------
#define BDIM 1024
#define SDIM 64
#define DDIM 768
#define POOLN 30
#define TOPK 4
#define SEQL 68          // TOPK + SDIM
#define CTOK 64
#define MROWS (BDIM*CTOK)    // 65536

#define OFF_RSIM (BDIM*CTOK*DDIM)               // 50331648
#define OFF_SIM  (OFF_RSIM + 1)                 // 50331649
#define OFF_IDX  (OFF_SIM + BDIM*POOLN)         // 50362369
#define OUT_TOTAL (OFF_IDX + BDIM*TOPK)         // 50366465

#define K2U32 384            // u32 per row of a split-bf16 matrix (768 bf16 / 2)
#define K2U4  96             // uint4 per row

// ---------------------------------------------------------------------------
// Scratch (static __device__ arrays — no runtime allocation)
// ---------------------------------------------------------------------------
__device__ float g_pnorm[POOLN * DDIM];
__device__ float g_xnorm[BDIM * DDIM];
__device__ int   g_idx[BDIM * TOPK];
__device__ float g_rsum[BDIM];
__device__ float g_bufB[(size_t)MROWS * DDIM];          // GEMM fp32 outputs
__device__ uint4 g_Ahi[(size_t)MROWS * K2U4];           // activation bf16-hi
__device__ uint4 g_Alo[(size_t)MROWS * K2U4];           // activation bf16-lo
__device__ uint4 g_Wahi[DDIM * K2U4];                   // w2a^T split
__device__ uint4 g_Walo[DDIM * K2U4];
__device__ uint4 g_Wbhi[DDIM * K2U4];                   // w2b^T split
__device__ uint4 g_Wblo[DDIM * K2U4];

// ---------------------------------------------------------------------------
// helpers
// ---------------------------------------------------------------------------
__device__ __forceinline__ uint32_t smem_u32(const void* p) {
    uint32_t a;
    asm("{ .reg .u64 t; cvta.to.shared.u64 t, %1; cvt.u32.u64 %0, t; }"
        : "=r"(a) : "l"(p));
    return a;
}

__device__ __forceinline__ void ldsm_x4(uint32_t* r, uint32_t addr) {
    asm volatile("ldmatrix.sync.aligned.m8n8.x4.shared.b16 {%0,%1,%2,%3}, [%4];"
        : "=r"(r[0]), "=r"(r[1]), "=r"(r[2]), "=r"(r[3]) : "r"(addr));
}

__device__ __forceinline__ void mma_bf16(float c[4], const uint32_t a[4],
                                         uint32_t b0, uint32_t b1) {
    asm volatile(
        "mma.sync.aligned.m16n8k16.row.col.f32.bf16.bf16.f32 "
        "{%0,%1,%2,%3}, {%4,%5,%6,%7}, {%8,%9}, {%0,%1,%2,%3};"
        : "+f"(c[0]), "+f"(c[1]), "+f"(c[2]), "+f"(c[3])
        : "r"(a[0]), "r"(a[1]), "r"(a[2]), "r"(a[3]), "r"(b0), "r"(b1));
}

__device__ __forceinline__ void cp16(uint32_t dst, const void* src) {
    asm volatile("cp.async.cg.shared.global [%0], [%1], 16;" :: "r"(dst), "l"(src));
}
#define CP_COMMIT() asm volatile("cp.async.commit_group;" ::: "memory")
#define CP_WAIT(n)  asm volatile("cp.async.wait_group %0;" :: "n"(n) : "memory")

// split fp32 pair -> packed bf16x2 hi + lo
__device__ __forceinline__ void split2(float a, float b, uint32_t& hi, uint32_t& lo) {
    __nv_bfloat16 ah = __float2bfloat16_rn(a), bh = __float2bfloat16_rn(b);
    float ar = a - __bfloat162float(ah), br = b - __bfloat162float(bh);
    __nv_bfloat16 al = __float2bfloat16_rn(ar), bl = __float2bfloat16_rn(br);
    hi = (uint32_t)__bfloat16_as_ushort(ah) | ((uint32_t)__bfloat16_as_ushort(bh) << 16);
    lo = (uint32_t)__bfloat16_as_ushort(al) | ((uint32_t)__bfloat16_as_ushort(bl) << 16);
}

// ---------------------------------------------------------------------------
// K1: prompt_norm
// ---------------------------------------------------------------------------
__global__ __launch_bounds__(256) void pnorm_kernel(const float* __restrict__ prompt) {
    int p = blockIdx.x;
    int tid = threadIdx.x;
    const float* row = prompt + (size_t)p * DDIM;
    float v0 = row[tid], v1 = row[tid + 256], v2 = row[tid + 512];
    float ssq = v0 * v0 + v1 * v1 + v2 * v2;
    __shared__ float sh[8];
    #pragma unroll
    for (int o = 16; o; o >>= 1) ssq += __shfl_down_sync(0xffffffffu, ssq, o);
    if ((tid & 31) == 0) sh[tid >> 5] = ssq;
    __syncthreads();
    if (tid < 32) {
        float v = (tid < 8) ? sh[tid] : 0.f;
        #pragma unroll
        for (int o = 4; o; o >>= 1) v += __shfl_down_sync(0xffffffffu, v, o);
        if (tid == 0) sh[0] = v;
    }
    __syncthreads();
    float rn = rsqrtf(fmaxf(sh[0], 1e-12f));
    float* dst = g_pnorm + (size_t)p * DDIM;
    dst[tid]       = v0 * rn;
    dst[tid + 256] = v1 * rn;
    dst[tid + 512] = v2 * rn;
}

// ---------------------------------------------------------------------------
// K2: x_mean + l2 normalize
// ---------------------------------------------------------------------------
__global__ __launch_bounds__(256) void xmean_norm_kernel(const float* __restrict__ x) {
    int b = blockIdx.x;
    int tid = threadIdx.x;
    float m[3];
    float ssq = 0.f;
    #pragma unroll
    for (int i = 0; i < 3; i++) {
        int d = tid + i * 256;
        float s = 0.f;
        #pragma unroll 8
        for (int si = 0; si < SDIM; si++)
            s += x[((size_t)b * SDIM + si) * DDIM + d];
        m[i] = s * (1.f / SDIM);
        ssq += m[i] * m[i];
    }
    __shared__ float sh[8];
    #pragma unroll
    for (int o = 16; o; o >>= 1) ssq += __shfl_down_sync(0xffffffffu, ssq, o);
    if ((tid & 31) == 0) sh[tid >> 5] = ssq;
    __syncthreads();
    if (tid < 32) {
        float v = (tid < 8) ? sh[tid] : 0.f;
        #pragma unroll
        for (int o = 4; o; o >>= 1) v += __shfl_down_sync(0xffffffffu, v, o);
        if (tid == 0) sh[0] = v;
    }
    __syncthreads();
    float rn = rsqrtf(fmaxf(sh[0], 1e-12f));
    #pragma unroll
    for (int i = 0; i < 3; i++)
        g_xnorm[(size_t)b * DDIM + tid + i * 256] = m[i] * rn;
}

// ---------------------------------------------------------------------------
// K3: similarity + top-4 + per-batch reduce_sim partial
// ---------------------------------------------------------------------------
__global__ __launch_bounds__(256) void sim_topk_kernel(float* __restrict__ out, int write_aux) {
    int b = blockIdx.x;
    int tid = threadIdx.x;
    __shared__ float sx[DDIM];
    __shared__ float ssim[32];
    for (int i = tid; i < DDIM; i += 256) sx[i] = g_xnorm[(size_t)b * DDIM + i];
    __syncthreads();
    int p = tid >> 3;
    int l8 = tid & 7;
    float acc = 0.f;
    if (p < POOLN) {
        const float* pr = g_pnorm + (size_t)p * DDIM;
        for (int k = l8; k < DDIM; k += 8) acc += sx[k] * pr[k];
    }
    #pragma unroll
    for (int o = 4; o; o >>= 1) acc += __shfl_down_sync(0xffffffffu, acc, o, 8);
    if (l8 == 0 && p < POOLN) ssim[p] = acc;
    __syncthreads();
    if (write_aux && tid < POOLN) out[OFF_SIM + (size_t)b * POOLN + tid] = ssim[tid];
    if (tid == 0) {
        bool used[POOLN];
        #pragma unroll
        for (int i = 0; i < POOLN; i++) used[i] = false;
        float rs = 0.f;
        for (int k = 0; k < TOPK; k++) {
            int best = 0;
            float bv = -3.4e38f;
            for (int pp = 0; pp < POOLN; pp++) {
                if (!used[pp] && ssim[pp] > bv) { bv = ssim[pp]; best = pp; }
            }
            used[best] = true;
            g_idx[b * TOPK + k] = best;
            if (write_aux) out[OFF_IDX + (size_t)b * TOPK + k] = (float)best;
            rs += bv;
        }
        g_rsum[b] = rs;
    }
}

// ---------------------------------------------------------------------------
// K3b: reduce_sim scalar
// ---------------------------------------------------------------------------
__global__ __launch_bounds__(256) void reduce_rsim_kernel(float* __restrict__ out) {
    int tid = threadIdx.x;
    float v = g_rsum[tid] + g_rsum[tid + 256] + g_rsum[tid + 512] + g_rsum[tid + 768];
    __shared__ float sh[8];
    #pragma unroll
    for (int o = 16; o; o >>= 1) v += __shfl_down_sync(0xffffffffu, v, o);
    if ((tid & 31) == 0) sh[tid >> 5] = v;
    __syncthreads();
    if (tid < 32) {
        float w = (tid < 8) ? sh[tid] : 0.f;
        #pragma unroll
        for (int o = 4; o; o >>= 1) w += __shfl_down_sync(0xffffffffu, w, o);
        if (tid == 0) out[OFF_RSIM] = w * (1.f / BDIM);
    }
}

// ---------------------------------------------------------------------------
// K-wprep: transpose 768x768 weight and split into bf16 hi/lo pairs.
// out layout: Wt[n][k] as u32 pairs along k.  grid (24,24), block (32,8)
// ---------------------------------------------------------------------------
__global__ __launch_bounds__(256) void wprep_kernel(
    const float* __restrict__ W, uint32_t* __restrict__ Whi, uint32_t* __restrict__ Wlo)
{
    __shared__ float t[32][33];
    int bxn = blockIdx.x;   // n tile
    int byk = blockIdx.y;   // k tile
    int tx = threadIdx.x, ty = threadIdx.y;
    #pragma unroll
    for (int i = 0; i < 4; i++) {
        int k = byk * 32 + ty + i * 8;
        t[ty + i * 8][tx] = W[(size_t)k * DDIM + bxn * 32 + tx];
    }
    __syncthreads();
    int tid = ty * 32 + tx;
    #pragma unroll
    for (int q = 0; q < 2; q++) {
        int idx = tid + q * 256;
        int nn = idx >> 4;         // 0..31
        int p  = idx & 15;         // k-pair within tile
        uint32_t hi, lo;
        split2(t[2 * p][nn], t[2 * p + 1][nn], hi, lo);
        size_t o = (size_t)(bxn * 32 + nn) * K2U32 + byk * 16 + p;
        Whi[o] = hi;
        Wlo[o] = lo;
    }
}

// ---------------------------------------------------------------------------
// K4: fused mlp_1 (token mixing).  grid = (12, B), block=256.
// Output: split-bf16 activation rows into g_Ahi/g_Alo.
// ---------------------------------------------------------------------------
__global__ __launch_bounds__(256) void mlp1_fused_kernel(
    const float* __restrict__ x_embed, const float* __restrict__ prompt,
    const float* __restrict__ w1a, const float* __restrict__ b1a,
    const float* __restrict__ g1a, const float* __restrict__ be1a,
    const float* __restrict__ w1b, const float* __restrict__ b1b,
    const float* __restrict__ g1b, const float* __restrict__ be1b)
{
    extern __shared__ float sm[];
    float* sW1a  = sm;              // 68*64 = 4352
    float* sW1b  = sm + 4352;       // 64*64 = 4096
    float* sA    = sm + 8448;       // 68*64 = 4352  (reused as H2, stride 65)
    float* sH    = sm + 12800;      // 64*65 = 4160
    float* sMean = sm + 16960;      // 64
    float* sRstd = sm + 17024;      // 64  -> total 17088 floats

    int b  = blockIdx.y;
    int d0 = blockIdx.x * 64;
    int tid = threadIdx.x;

    for (int i = tid; i < SEQL * 64; i += 256) sW1a[i] = w1a[i];
    for (int i = tid; i < 64 * 64;  i += 256) sW1b[i] = w1b[i];
    for (int i = tid; i < SEQL * 64; i += 256) {
        int s = i >> 6, dd = i & 63;
        float v;
        if (s < TOPK)
            v = prompt[(size_t)g_idx[b * TOPK + s] * DDIM + d0 + dd];
        else
            v = x_embed[((size_t)b * SDIM + (s - TOPK)) * DDIM + d0 + dd];
        sA[i] = v;
    }
    __syncthreads();

    int tx = tid & 15;
    int ty = tid >> 4;
    float acc[4][4];
    #pragma unroll
    for (int i = 0; i < 4; i++)
        #pragma unroll
        for (int j = 0; j < 4; j++) acc[i][j] = 0.f;

    #pragma unroll 4
    for (int s = 0; s < SEQL; s++) {
        float4 a4 = *(const float4*)&sA[s * 64 + ty * 4];
        float4 w4 = *(const float4*)&sW1a[s * 64 + tx * 4];
        float a[4] = {a4.x, a4.y, a4.z, a4.w};
        float w[4] = {w4.x, w4.y, w4.z, w4.w};
        #pragma unroll
        for (int i = 0; i < 4; i++)
            #pragma unroll
            for (int j = 0; j < 4; j++) acc[i][j] += a[i] * w[j];
    }
    #pragma unroll
    for (int i = 0; i < 4; i++) {
        int r = ty * 4 + i;
        #pragma unroll
        for (int j = 0; j < 4; j++) {
            int c = tx * 4 + j;
            sH[r * 65 + c] = fmaxf(acc[i][j] + b1a[c], 0.f);
        }
    }
    __syncthreads();
    if (tid < 64) {
        float s = 0.f, sq = 0.f;
        #pragma unroll 8
        for (int c = 0; c < 64; c++) { float v = sH[tid * 65 + c]; s += v; sq += v * v; }
        float m = s * (1.f / 64.f);
        float var = sq * (1.f / 64.f) - m * m;
        sMean[tid] = m;
        sRstd[tid] = rsqrtf(fmaxf(var, 0.f) + 1e-5f);
    }
    __syncthreads();
    for (int i = tid; i < 4096; i += 256) {
        int r = i >> 6, c = i & 63;
        sH[r * 65 + c] = (sH[r * 65 + c] - sMean[r]) * sRstd[r] * g1a[c] + be1a[c];
    }
    __syncthreads();

    #pragma unroll
    for (int i = 0; i < 4; i++)
        #pragma unroll
        for (int j = 0; j < 4; j++) acc[i][j] = 0.f;
    #pragma unroll 8
    for (int k = 0; k < 64; k++) {
        float a[4];
        #pragma unroll
        for (int i = 0; i < 4; i++) a[i] = sH[(ty * 4 + i) * 65 + k];
        float4 w4 = *(const float4*)&sW1b[k * 64 + tx * 4];
        float w[4] = {w4.x, w4.y, w4.z, w4.w};
        #pragma unroll
        for (int i = 0; i < 4; i++)
            #pragma unroll
            for (int j = 0; j < 4; j++) acc[i][j] += a[i] * w[j];
    }
    #pragma unroll
    for (int i = 0; i < 4; i++) {
        int r = ty * 4 + i;
        #pragma unroll
        for (int j = 0; j < 4; j++) {
            int c = tx * 4 + j;
            sA[r * 65 + c] = fmaxf(acc[i][j] + b1b[c], 0.f);
        }
    }
    __syncthreads();
    if (tid < 64) {
        float s = 0.f, sq = 0.f;
        #pragma unroll 8
        for (int c = 0; c < 64; c++) { float v = sA[tid * 65 + c]; s += v; sq += v * v; }
        float m = s * (1.f / 64.f);
        float var = sq * (1.f / 64.f) - m * m;
        sMean[tid] = m;
        sRstd[tid] = rsqrtf(fmaxf(var, 0.f) + 1e-5f);
    }
    __syncthreads();
    for (int i = tid; i < 4096; i += 256) {
        int r = i >> 6, c = i & 63;
        sA[r * 65 + c] = (sA[r * 65 + c] - sMean[r]) * sRstd[r] * g1b[c] + be1b[c];
    }
    __syncthreads();
    // split-bf16 transposed write: element (b*64+c, d0+dd) = h2[dd][c]
    uint32_t* Ah = (uint32_t*)g_Ahi;
    uint32_t* Al = (uint32_t*)g_Alo;
    for (int i = tid; i < 2048; i += 256) {
        int c = i >> 5;
        int d2 = (i & 31) * 2;
        uint32_t hi, lo;
        split2(sA[d2 * 65 + c], sA[(d2 + 1) * 65 + c], hi, lo);
        size_t o = ((size_t)b * CTOK + c) * K2U32 + (d0 >> 1) + (d2 >> 1);
        Ah[o] = hi;
        Al[o] = lo;
    }
}

// ---------------------------------------------------------------------------
// K5/K7: split-bf16 mma.sync GEMM   C = relu(A @ W + bias)
//  A: split rows (Ahi/Alo [M][384] u32, bf16 pairs along k)
//  B: transposed split (Bhi/Blo [N][384] u32, B[n][k] = W[k][n])
//  D += Ah*Bh + Ah*Bl + Al*Bh   (al*bl ~2^-18 dropped)
//  Block 128x128, k-tile 32 bf16, 2-stage cp.async, 8 warps of 64x32,
//  m16n8k16 mma, ldmatrix A-frags, direct LDS.32 B-frags.
//  smem rows padded to 80B -> conflict-free LDSM and LDS phases.
// ---------------------------------------------------------------------------
#define SSTRB 80                 // bytes per smem row (40 bf16)
#define TILEB (128 * SSTRB)      // 10240
#define STAGEB (4 * TILEB)       // 40960
#define GEMM_SMEM (2 * STAGEB)   // 81920
#define NKT 24                   // 768 / 32

__global__ __launch_bounds__(256, 1) void gemm_bf16s_kernel(
    const uint4* __restrict__ Ahi, const uint4* __restrict__ Alo,
    const uint4* __restrict__ Bhi, const uint4* __restrict__ Blo,
    const float* __restrict__ bias, float* __restrict__ C)
{
    extern __shared__ char smc[];
    const uint32_t sbase = smem_u32(smc);
    const int tid  = threadIdx.x;
    const int lane = tid & 31;
    const int wid  = tid >> 5;
    const int bx   = blockIdx.x;   // N tile (0..5)
    const int by   = blockIdx.y;   // M tile (0..511)

    const int warpM = (wid & 1) * 64;
    const int warpN = (wid >> 1) * 32;
    const int g  = lane >> 2;      // 0..7
    const int t4 = lane & 3;       // 0..3

    // loader mapping: 2 threads per row, each 2 uint4 of the 4 per (row, ktile)
    const int lrow = tid >> 1;            // 0..127
    const int ljj  = (tid & 1) * 2;       // 0 or 2
    const uint4* srcRow[4];
    srcRow[0] = Ahi + ((size_t)(by * 128) + lrow) * K2U4 + ljj;
    srcRow[1] = Alo + ((size_t)(by * 128) + lrow) * K2U4 + ljj;
    srcRow[2] = Bhi + ((size_t)(bx * 128) + lrow) * K2U4 + ljj;
    srcRow[3] = Blo + ((size_t)(bx * 128) + lrow) * K2U4 + ljj;
    const uint32_t ldst = lrow * SSTRB + ljj * 16;

    // ldmatrix per-lane address offset within an A tile (for a 16-row block)
    const uint32_t aoff = ((lane & 7) + ((lane >> 3) & 1) * 8) * SSTRB
                        + (lane >> 4) * 16;

    float acc[4][4][4];
    #pragma unroll
    for (int mi = 0; mi < 4; mi++)
        #pragma unroll
        for (int ni = 0; ni < 4; ni++)
            #pragma unroll
            for (int e = 0; e < 4; e++) acc[mi][ni][e] = 0.f;

    // preload stages 0, 1
    #pragma unroll
    for (int s = 0; s < 2; s++) {
        uint32_t sb = sbase + s * STAGEB + ldst;
        #pragma unroll
        for (int k = 0; k < 4; k++) {
            const uint4* sp = srcRow[k] + s * 4;
            cp16(sb + k * TILEB, sp);
            cp16(sb + k * TILEB + 16, sp + 1);
        }
        CP_COMMIT();
    }
    CP_WAIT(1);
    __syncthreads();

    for (int t = 0; t < NKT; t++) {
        const int s = t & 1;
        const uint32_t Ab  = sbase + s * STAGEB;
        const uint32_t Alb = Ab + TILEB;
        const uint32_t* Bh32 = (const uint32_t*)(smc + s * STAGEB + 2 * TILEB);
        const uint32_t* Bl32 = (const uint32_t*)(smc + s * STAGEB + 3 * TILEB);

        #pragma unroll
        for (int kk = 0; kk < 2; kk++) {
            uint32_t ah[4][4], al[4][4];
            #pragma unroll
            for (int mi = 0; mi < 4; mi++) {
                uint32_t ro = (warpM + mi * 16) * SSTRB + aoff + kk * 32;
                ldsm_x4(ah[mi], Ab + ro);
                ldsm_x4(al[mi], Alb + ro);
            }
            uint32_t bh[4][2], bl[4][2];
            #pragma unroll
            for (int ni = 0; ni < 4; ni++) {
                int n = warpN + ni * 8 + g;
                int o = n * 20 + kk * 8 + t4;    // 20 u32 per 80B row
                bh[ni][0] = Bh32[o];
                bh[ni][1] = Bh32[o + 4];
                bl[ni][0] = Bl32[o];
                bl[ni][1] = Bl32[o + 4];
            }
            // term order: hh, hl, lh  (16 independent mmas between acc reuse)
            #pragma unroll
            for (int mi = 0; mi < 4; mi++)
                #pragma unroll
                for (int ni = 0; ni < 4; ni++)
                    mma_bf16(acc[mi][ni], ah[mi], bh[ni][0], bh[ni][1]);
            #pragma unroll
            for (int mi = 0; mi < 4; mi++)
                #pragma unroll
                for (int ni = 0; ni < 4; ni++)
                    mma_bf16(acc[mi][ni], ah[mi], bl[ni][0], bl[ni][1]);
            #pragma unroll
            for (int mi = 0; mi < 4; mi++)
                #pragma unroll
                for (int ni = 0; ni < 4; ni++)
                    mma_bf16(acc[mi][ni], al[mi], bh[ni][0], bh[ni][1]);
        }
        __syncthreads();
        if (t + 2 < NKT) {
            uint32_t sb = sbase + s * STAGEB + ldst;
            #pragma unroll
            for (int k = 0; k < 4; k++) {
                const uint4* sp = srcRow[k] + (t + 2) * 4;
                cp16(sb + k * TILEB, sp);
                cp16(sb + k * TILEB + 16, sp + 1);
            }
            CP_COMMIT();
            CP_WAIT(1);
        } else {
            CP_WAIT(0);
        }
        __syncthreads();
    }

    // epilogue: bias + relu
    #pragma unroll
    for (int mi = 0; mi < 4; mi++) {
        size_t row0 = (size_t)by * 128 + warpM + mi * 16 + g;
        #pragma unroll
        for (int ni = 0; ni < 4; ni++) {
            int col = bx * 128 + warpN + ni * 8 + t4 * 2;
            float b0 = bias[col], b1 = bias[col + 1];
            float2 v0, v1;
            v0.x = fmaxf(acc[mi][ni][0] + b0, 0.f);
            v0.y = fmaxf(acc[mi][ni][1] + b1, 0.f);
            v1.x = fmaxf(acc[mi][ni][2] + b0, 0.f);
            v1.y = fmaxf(acc[mi][ni][3] + b1, 0.f);
            *(float2*)&C[row0 * DDIM + col]       = v0;
            *(float2*)&C[(row0 + 8) * DDIM + col] = v1;
        }
    }
}

// ---------------------------------------------------------------------------
// K6: LayerNorm over 768 -> split-bf16 output (feeds next GEMM)
// ---------------------------------------------------------------------------
__global__ __launch_bounds__(256) void ln_rows_bf16_kernel(
    const float* __restrict__ in, uint32_t* __restrict__ outh,
    uint32_t* __restrict__ outl,
    const float* __restrict__ g, const float* __restrict__ be)
{
    size_t row = blockIdx.x;
    int tid = threadIdx.x;
    const float* p = in + row * DDIM;
    float v0 = p[tid], v1 = p[tid + 256], v2 = p[tid + 512];
    float s = v0 + v1 + v2;
    float sq = v0 * v0 + v1 * v1 + v2 * v2;
    __shared__ float sh[16];
    __shared__ float y[DDIM];
    #pragma unroll
    for (int o = 16; o; o >>= 1) {
        s  += __shfl_down_sync(0xffffffffu, s, o);
        sq += __shfl_down_sync(0xffffffffu, sq, o);
    }
    if ((tid & 31) == 0) { sh[tid >> 5] = s; sh[8 + (tid >> 5)] = sq; }
    __syncthreads();
    if (tid < 32) {
        float a = (tid < 8) ? sh[tid] : 0.f;
        float c = (tid < 8) ? sh[8 + tid] : 0.f;
        #pragma unroll
        for (int o = 4; o; o >>= 1) {
            a += __shfl_down_sync(0xffffffffu, a, o);
            c += __shfl_down_sync(0xffffffffu, c, o);
        }
        if (tid == 0) { sh[0] = a; sh[1] = c; }
    }
    __syncthreads();
    float mean = sh[0] * (1.f / DDIM);
    float var  = sh[1] * (1.f / DDIM) - mean * mean;
    float rstd = rsqrtf(fmaxf(var, 0.f) + 1e-5f);
    y[tid]       = (v0 - mean) * rstd * g[tid]       + be[tid];
    y[tid + 256] = (v1 - mean) * rstd * g[tid + 256] + be[tid + 256];
    y[tid + 512] = (v2 - mean) * rstd * g[tid + 512] + be[tid + 512];
    __syncthreads();
    #pragma unroll
    for (int q = 0; q < 2; q++) {
        int pr = tid + q * 256;
        if (pr < K2U32) {
            uint32_t hi, lo;
            split2(y[2 * pr], y[2 * pr + 1], hi, lo);
            outh[row * K2U32 + pr] = hi;
            outl[row * K2U32 + pr] = lo;
        }
    }
}

// ---------------------------------------------------------------------------
// K8: final LayerNorm -> fp32 out
// ---------------------------------------------------------------------------
__global__ __launch_bounds__(256) void ln_rows_kernel(
    const float* __restrict__ in, float* __restrict__ out,
    const float* __restrict__ g, const float* __restrict__ be)
{
    size_t row = blockIdx.x;
    int tid = threadIdx.x;
    const float* p = in + row * DDIM;
    float* q = out + row * DDIM;
    float v0 = p[tid], v1 = p[tid + 256], v2 = p[tid + 512];
    float s = v0 + v1 + v2;
    float sq = v0 * v0 + v1 * v1 + v2 * v2;
    __shared__ float sh[16];
    #pragma unroll
    for (int o = 16; o; o >>= 1) {
        s  += __shfl_down_sync(0xffffffffu, s, o);
        sq += __shfl_down_sync(0xffffffffu, sq, o);
    }
    if ((tid & 31) == 0) { sh[tid >> 5] = s; sh[8 + (tid >> 5)] = sq; }
    __syncthreads();
    if (tid < 32) {
        float a = (tid < 8) ? sh[tid] : 0.f;
        float c = (tid < 8) ? sh[8 + tid] : 0.f;
        #pragma unroll
        for (int o = 4; o; o >>= 1) {
            a += __shfl_down_sync(0xffffffffu, a, o);
            c += __shfl_down_sync(0xffffffffu, c, o);
        }
        if (tid == 0) { sh[0] = a; sh[1] = c; }
    }
    __syncthreads();
    float mean = sh[0] * (1.f / DDIM);
    float var  = sh[1] * (1.f / DDIM) - mean * mean;
    float rstd = rsqrtf(fmaxf(var, 0.f) + 1e-5f);
    q[tid]       = (v0 - mean) * rstd * g[tid]       + be[tid];
    q[tid + 256] = (v1 - mean) * rstd * g[tid + 256] + be[tid + 256];
    q[tid + 512] = (v2 - mean) * rstd * g[tid + 512] + be[tid + 512];
}

// ---------------------------------------------------------------------------
// Launch
// ---------------------------------------------------------------------------
extern "C" void kernel_launch(void* const* d_in, const int* in_sizes, int n_in,
                              void* d_out, int out_size)
{
    const float* x_embed = (const float*)d_in[0];
    const float* prompt  = (const float*)d_in[1];
    const float* w1a  = (const float*)d_in[2];
    const float* b1a  = (const float*)d_in[3];
    const float* g1a  = (const float*)d_in[4];
    const float* be1a = (const float*)d_in[5];
    const float* w1b  = (const float*)d_in[6];
    const float* b1b  = (const float*)d_in[7];
    const float* g1b  = (const float*)d_in[8];
    const float* be1b = (const float*)d_in[9];
    const float* w2a  = (const float*)d_in[10];
    const float* b2a  = (const float*)d_in[11];
    const float* g2a  = (const float*)d_in[12];
    const float* be2a = (const float*)d_in[13];
    const float* w2b  = (const float*)d_in[14];
    const float* b2b  = (const float*)d_in[15];
    const float* g2b  = (const float*)d_in[16];
    const float* be2b = (const float*)d_in[17];
    float* out = (float*)d_out;

    int write_aux = (out_size >= OUT_TOTAL) ? 1 : 0;

    float* bufB = nullptr;
    uint4 *Ahi, *Alo, *Wahi, *Walo, *Wbhi, *Wblo;
    cudaGetSymbolAddress((void**)&bufB, g_bufB);
    cudaGetSymbolAddress((void**)&Ahi,  g_Ahi);
    cudaGetSymbolAddress((void**)&Alo,  g_Alo);
    cudaGetSymbolAddress((void**)&Wahi, g_Wahi);
    cudaGetSymbolAddress((void**)&Walo, g_Walo);
    cudaGetSymbolAddress((void**)&Wbhi, g_Wbhi);
    cudaGetSymbolAddress((void**)&Wblo, g_Wblo);

    // prompt selection pipeline
    pnorm_kernel<<<POOLN, 256>>>(prompt);
    xmean_norm_kernel<<<BDIM, 256>>>(x_embed);
    sim_topk_kernel<<<BDIM, 256>>>(out, write_aux);
    if (write_aux) reduce_rsim_kernel<<<1, 256>>>(out);

    // weight transpose+split
    wprep_kernel<<<dim3(24, 24), dim3(32, 8)>>>(w2a, (uint32_t*)Wahi, (uint32_t*)Walo);
    wprep_kernel<<<dim3(24, 24), dim3(32, 8)>>>(w2b, (uint32_t*)Wbhi, (uint32_t*)Wblo);

    // fused mlp_1 -> split-bf16 activations
    int mlp1_smem = 17088 * (int)sizeof(float);
    cudaFuncSetAttribute(mlp1_fused_kernel,
                         cudaFuncAttributeMaxDynamicSharedMemorySize, mlp1_smem);
    mlp1_fused_kernel<<<dim3(DDIM / 64, BDIM), 256, mlp1_smem>>>(
        x_embed, prompt, w1a, b1a, g1a, be1a, w1b, b1b, g1b, be1b);

    // mlp_2: split-bf16 mma GEMM + LN stages
    cudaFuncSetAttribute(gemm_bf16s_kernel,
                         cudaFuncAttributeMaxDynamicSharedMemorySize, GEMM_SMEM);
    dim3 ggrid(DDIM / 128, MROWS / 128);   // (6, 512)
    gemm_bf16s_kernel<<<ggrid, 256, GEMM_SMEM>>>(Ahi, Alo, Wahi, Walo, b2a, bufB);
    ln_rows_bf16_kernel<<<MROWS, 256>>>(bufB, (uint32_t*)Ahi, (uint32_t*)Alo, g2a, be2a);
    gemm_bf16s_kernel<<<ggrid, 256, GEMM_SMEM>>>(Ahi, Alo, Wbhi, Wblo, b2b, bufB);
    ln_rows_kernel<<<MROWS, 256>>>(bufB, out, g2b, be2b);
}

// round 8
// speedup vs baseline: 1.1145x; 1.1145x over previous
#include <cuda_runtime.h>
#include <cuda_bf16.h>
#include <cstdint>
#include <cstddef>

// ---------------------------------------------------------------------------
// Problem constants
// ---------------------------------------------------------------------------
#define BDIM 1024
#define SDIM 64
#define DDIM 768
#define POOLN 30
#define TOPK 4
#define SEQL 68          // TOPK + SDIM
#define CTOK 64
#define MROWS (BDIM*CTOK)    // 65536

#define OFF_RSIM (BDIM*CTOK*DDIM)               // 50331648
#define OFF_SIM  (OFF_RSIM + 1)                 // 50331649
#define OFF_IDX  (OFF_SIM + BDIM*POOLN)         // 50362369
#define OUT_TOTAL (OFF_IDX + BDIM*TOPK)         // 50366465

#define K2U32 384            // u32 per row of a split-bf16 matrix (768 bf16 / 2)
#define K2U4  96             // uint4 per row

// ---------------------------------------------------------------------------
// Scratch (static __device__ arrays — no runtime allocation)
// ---------------------------------------------------------------------------
__device__ float g_pnorm[POOLN * DDIM];
__device__ float g_xnorm[BDIM * DDIM];
__device__ int   g_idx[BDIM * TOPK];
__device__ float g_rsum[BDIM];
__device__ float g_bufB[(size_t)MROWS * DDIM];          // GEMM fp32 outputs
__device__ uint4 g_Ahi[(size_t)MROWS * K2U4];           // activation bf16-hi
__device__ uint4 g_Alo[(size_t)MROWS * K2U4];           // activation bf16-lo
__device__ uint4 g_Wahi[DDIM * K2U4];                   // w2a^T split
__device__ uint4 g_Walo[DDIM * K2U4];
__device__ uint4 g_Wbhi[DDIM * K2U4];                   // w2b^T split
__device__ uint4 g_Wblo[DDIM * K2U4];

// ---------------------------------------------------------------------------
// helpers
// ---------------------------------------------------------------------------
__device__ __forceinline__ uint32_t smem_u32(const void* p) {
    uint32_t a;
    asm("{ .reg .u64 t; cvta.to.shared.u64 t, %1; cvt.u32.u64 %0, t; }"
        : "=r"(a) : "l"(p));
    return a;
}

__device__ __forceinline__ void ldsm_x4(uint32_t* r, uint32_t addr) {
    asm volatile("ldmatrix.sync.aligned.m8n8.x4.shared.b16 {%0,%1,%2,%3}, [%4];"
        : "=r"(r[0]), "=r"(r[1]), "=r"(r[2]), "=r"(r[3]) : "r"(addr));
}

__device__ __forceinline__ void mma_bf16(float c[4], const uint32_t a[4],
                                         uint32_t b0, uint32_t b1) {
    asm volatile(
        "mma.sync.aligned.m16n8k16.row.col.f32.bf16.bf16.f32 "
        "{%0,%1,%2,%3}, {%4,%5,%6,%7}, {%8,%9}, {%0,%1,%2,%3};"
        : "+f"(c[0]), "+f"(c[1]), "+f"(c[2]), "+f"(c[3])
        : "r"(a[0]), "r"(a[1]), "r"(a[2]), "r"(a[3]), "r"(b0), "r"(b1));
}

__device__ __forceinline__ void cp16(uint32_t dst, const void* src) {
    asm volatile("cp.async.cg.shared.global [%0], [%1], 16;" :: "r"(dst), "l"(src));
}
#define CP_COMMIT() asm volatile("cp.async.commit_group;" ::: "memory")
#define CP_WAIT(n)  asm volatile("cp.async.wait_group %0;" :: "n"(n) : "memory")

// split fp32 pair -> packed bf16x2 hi + lo
__device__ __forceinline__ void split2(float a, float b, uint32_t& hi, uint32_t& lo) {
    __nv_bfloat16 ah = __float2bfloat16_rn(a), bh = __float2bfloat16_rn(b);
    float ar = a - __bfloat162float(ah), br = b - __bfloat162float(bh);
    __nv_bfloat16 al = __float2bfloat16_rn(ar), bl = __float2bfloat16_rn(br);
    hi = (uint32_t)__bfloat16_as_ushort(ah) | ((uint32_t)__bfloat16_as_ushort(bh) << 16);
    lo = (uint32_t)__bfloat16_as_ushort(al) | ((uint32_t)__bfloat16_as_ushort(bl) << 16);
}

// ---------------------------------------------------------------------------
// K1: prompt_norm
// ---------------------------------------------------------------------------
__global__ __launch_bounds__(256) void pnorm_kernel(const float* __restrict__ prompt) {
    int p = blockIdx.x;
    int tid = threadIdx.x;
    const float* row = prompt + (size_t)p * DDIM;
    float v0 = row[tid], v1 = row[tid + 256], v2 = row[tid + 512];
    float ssq = v0 * v0 + v1 * v1 + v2 * v2;
    __shared__ float sh[8];
    #pragma unroll
    for (int o = 16; o; o >>= 1) ssq += __shfl_down_sync(0xffffffffu, ssq, o);
    if ((tid & 31) == 0) sh[tid >> 5] = ssq;
    __syncthreads();
    if (tid < 32) {
        float v = (tid < 8) ? sh[tid] : 0.f;
        #pragma unroll
        for (int o = 4; o; o >>= 1) v += __shfl_down_sync(0xffffffffu, v, o);
        if (tid == 0) sh[0] = v;
    }
    __syncthreads();
    float rn = rsqrtf(fmaxf(sh[0], 1e-12f));
    float* dst = g_pnorm + (size_t)p * DDIM;
    dst[tid]       = v0 * rn;
    dst[tid + 256] = v1 * rn;
    dst[tid + 512] = v2 * rn;
}

// ---------------------------------------------------------------------------
// K2: x_mean + l2 normalize
// ---------------------------------------------------------------------------
__global__ __launch_bounds__(256) void xmean_norm_kernel(const float* __restrict__ x) {
    int b = blockIdx.x;
    int tid = threadIdx.x;
    float m[3];
    float ssq = 0.f;
    #pragma unroll
    for (int i = 0; i < 3; i++) {
        int d = tid + i * 256;
        float s = 0.f;
        #pragma unroll 8
        for (int si = 0; si < SDIM; si++)
            s += x[((size_t)b * SDIM + si) * DDIM + d];
        m[i] = s * (1.f / SDIM);
        ssq += m[i] * m[i];
    }
    __shared__ float sh[8];
    #pragma unroll
    for (int o = 16; o; o >>= 1) ssq += __shfl_down_sync(0xffffffffu, ssq, o);
    if ((tid & 31) == 0) sh[tid >> 5] = ssq;
    __syncthreads();
    if (tid < 32) {
        float v = (tid < 8) ? sh[tid] : 0.f;
        #pragma unroll
        for (int o = 4; o; o >>= 1) v += __shfl_down_sync(0xffffffffu, v, o);
        if (tid == 0) sh[0] = v;
    }
    __syncthreads();
    float rn = rsqrtf(fmaxf(sh[0], 1e-12f));
    #pragma unroll
    for (int i = 0; i < 3; i++)
        g_xnorm[(size_t)b * DDIM + tid + i * 256] = m[i] * rn;
}

// ---------------------------------------------------------------------------
// K3: similarity + top-4 + per-batch reduce_sim partial
// ---------------------------------------------------------------------------
__global__ __launch_bounds__(256) void sim_topk_kernel(float* __restrict__ out, int write_aux) {
    int b = blockIdx.x;
    int tid = threadIdx.x;
    __shared__ float sx[DDIM];
    __shared__ float ssim[32];
    for (int i = tid; i < DDIM; i += 256) sx[i] = g_xnorm[(size_t)b * DDIM + i];
    __syncthreads();
    int p = tid >> 3;
    int l8 = tid & 7;
    float acc = 0.f;
    if (p < POOLN) {
        const float* pr = g_pnorm + (size_t)p * DDIM;
        for (int k = l8; k < DDIM; k += 8) acc += sx[k] * pr[k];
    }
    #pragma unroll
    for (int o = 4; o; o >>= 1) acc += __shfl_down_sync(0xffffffffu, acc, o, 8);
    if (l8 == 0 && p < POOLN) ssim[p] = acc;
    __syncthreads();
    if (write_aux && tid < POOLN) out[OFF_SIM + (size_t)b * POOLN + tid] = ssim[tid];
    if (tid == 0) {
        bool used[POOLN];
        #pragma unroll
        for (int i = 0; i < POOLN; i++) used[i] = false;
        float rs = 0.f;
        for (int k = 0; k < TOPK; k++) {
            int best = 0;
            float bv = -3.4e38f;
            for (int pp = 0; pp < POOLN; pp++) {
                if (!used[pp] && ssim[pp] > bv) { bv = ssim[pp]; best = pp; }
            }
            used[best] = true;
            g_idx[b * TOPK + k] = best;
            if (write_aux) out[OFF_IDX + (size_t)b * TOPK + k] = (float)best;
            rs += bv;
        }
        g_rsum[b] = rs;
    }
}

// ---------------------------------------------------------------------------
// K3b: reduce_sim scalar
// ---------------------------------------------------------------------------
__global__ __launch_bounds__(256) void reduce_rsim_kernel(float* __restrict__ out) {
    int tid = threadIdx.x;
    float v = g_rsum[tid] + g_rsum[tid + 256] + g_rsum[tid + 512] + g_rsum[tid + 768];
    __shared__ float sh[8];
    #pragma unroll
    for (int o = 16; o; o >>= 1) v += __shfl_down_sync(0xffffffffu, v, o);
    if ((tid & 31) == 0) sh[tid >> 5] = v;
    __syncthreads();
    if (tid < 32) {
        float w = (tid < 8) ? sh[tid] : 0.f;
        #pragma unroll
        for (int o = 4; o; o >>= 1) w += __shfl_down_sync(0xffffffffu, w, o);
        if (tid == 0) out[OFF_RSIM] = w * (1.f / BDIM);
    }
}

// ---------------------------------------------------------------------------
// K-wprep: transpose 768x768 weight and split into bf16 hi/lo pairs.
// out layout: Wt[n][k] as u32 pairs along k.  grid (24,24), block (32,8)
// ---------------------------------------------------------------------------
__global__ __launch_bounds__(256) void wprep_kernel(
    const float* __restrict__ W, uint32_t* __restrict__ Whi, uint32_t* __restrict__ Wlo)
{
    __shared__ float t[32][33];
    int bxn = blockIdx.x;   // n tile
    int byk = blockIdx.y;   // k tile
    int tx = threadIdx.x, ty = threadIdx.y;
    #pragma unroll
    for (int i = 0; i < 4; i++) {
        int k = byk * 32 + ty + i * 8;
        t[ty + i * 8][tx] = W[(size_t)k * DDIM + bxn * 32 + tx];
    }
    __syncthreads();
    int tid = ty * 32 + tx;
    #pragma unroll
    for (int q = 0; q < 2; q++) {
        int idx = tid + q * 256;
        int nn = idx >> 4;         // 0..31
        int p  = idx & 15;         // k-pair within tile
        uint32_t hi, lo;
        split2(t[2 * p][nn], t[2 * p + 1][nn], hi, lo);
        size_t o = (size_t)(bxn * 32 + nn) * K2U32 + byk * 16 + p;
        Whi[o] = hi;
        Wlo[o] = lo;
    }
}

// ---------------------------------------------------------------------------
// K4: fused mlp_1 (token mixing).  grid = (12, B), block=256.
// Output: split-bf16 activation rows into g_Ahi/g_Alo.
// ---------------------------------------------------------------------------
__global__ __launch_bounds__(256) void mlp1_fused_kernel(
    const float* __restrict__ x_embed, const float* __restrict__ prompt,
    const float* __restrict__ w1a, const float* __restrict__ b1a,
    const float* __restrict__ g1a, const float* __restrict__ be1a,
    const float* __restrict__ w1b, const float* __restrict__ b1b,
    const float* __restrict__ g1b, const float* __restrict__ be1b)
{
    extern __shared__ float sm[];
    float* sW1a  = sm;              // 68*64 = 4352
    float* sW1b  = sm + 4352;       // 64*64 = 4096
    float* sA    = sm + 8448;       // 68*64 = 4352  (reused as H2, stride 65)
    float* sH    = sm + 12800;      // 64*65 = 4160
    float* sMean = sm + 16960;      // 64
    float* sRstd = sm + 17024;      // 64  -> total 17088 floats

    int b  = blockIdx.y;
    int d0 = blockIdx.x * 64;
    int tid = threadIdx.x;

    for (int i = tid; i < SEQL * 64; i += 256) sW1a[i] = w1a[i];
    for (int i = tid; i < 64 * 64;  i += 256) sW1b[i] = w1b[i];
    for (int i = tid; i < SEQL * 64; i += 256) {
        int s = i >> 6, dd = i & 63;
        float v;
        if (s < TOPK)
            v = prompt[(size_t)g_idx[b * TOPK + s] * DDIM + d0 + dd];
        else
            v = x_embed[((size_t)b * SDIM + (s - TOPK)) * DDIM + d0 + dd];
        sA[i] = v;
    }
    __syncthreads();

    int tx = tid & 15;
    int ty = tid >> 4;
    float acc[4][4];
    #pragma unroll
    for (int i = 0; i < 4; i++)
        #pragma unroll
        for (int j = 0; j < 4; j++) acc[i][j] = 0.f;

    #pragma unroll 4
    for (int s = 0; s < SEQL; s++) {
        float4 a4 = *(const float4*)&sA[s * 64 + ty * 4];
        float4 w4 = *(const float4*)&sW1a[s * 64 + tx * 4];
        float a[4] = {a4.x, a4.y, a4.z, a4.w};
        float w[4] = {w4.x, w4.y, w4.z, w4.w};
        #pragma unroll
        for (int i = 0; i < 4; i++)
            #pragma unroll
            for (int j = 0; j < 4; j++) acc[i][j] += a[i] * w[j];
    }
    #pragma unroll
    for (int i = 0; i < 4; i++) {
        int r = ty * 4 + i;
        #pragma unroll
        for (int j = 0; j < 4; j++) {
            int c = tx * 4 + j;
            sH[r * 65 + c] = fmaxf(acc[i][j] + b1a[c], 0.f);
        }
    }
    __syncthreads();
    if (tid < 64) {
        float s = 0.f, sq = 0.f;
        #pragma unroll 8
        for (int c = 0; c < 64; c++) { float v = sH[tid * 65 + c]; s += v; sq += v * v; }
        float m = s * (1.f / 64.f);
        float var = sq * (1.f / 64.f) - m * m;
        sMean[tid] = m;
        sRstd[tid] = rsqrtf(fmaxf(var, 0.f) + 1e-5f);
    }
    __syncthreads();
    for (int i = tid; i < 4096; i += 256) {
        int r = i >> 6, c = i & 63;
        sH[r * 65 + c] = (sH[r * 65 + c] - sMean[r]) * sRstd[r] * g1a[c] + be1a[c];
    }
    __syncthreads();

    #pragma unroll
    for (int i = 0; i < 4; i++)
        #pragma unroll
        for (int j = 0; j < 4; j++) acc[i][j] = 0.f;
    #pragma unroll 8
    for (int k = 0; k < 64; k++) {
        float a[4];
        #pragma unroll
        for (int i = 0; i < 4; i++) a[i] = sH[(ty * 4 + i) * 65 + k];
        float4 w4 = *(const float4*)&sW1b[k * 64 + tx * 4];
        float w[4] = {w4.x, w4.y, w4.z, w4.w};
        #pragma unroll
        for (int i = 0; i < 4; i++)
            #pragma unroll
            for (int j = 0; j < 4; j++) acc[i][j] += a[i] * w[j];
    }
    #pragma unroll
    for (int i = 0; i < 4; i++) {
        int r = ty * 4 + i;
        #pragma unroll
        for (int j = 0; j < 4; j++) {
            int c = tx * 4 + j;
            sA[r * 65 + c] = fmaxf(acc[i][j] + b1b[c], 0.f);
        }
    }
    __syncthreads();
    if (tid < 64) {
        float s = 0.f, sq = 0.f;
        #pragma unroll 8
        for (int c = 0; c < 64; c++) { float v = sA[tid * 65 + c]; s += v; sq += v * v; }
        float m = s * (1.f / 64.f);
        float var = sq * (1.f / 64.f) - m * m;
        sMean[tid] = m;
        sRstd[tid] = rsqrtf(fmaxf(var, 0.f) + 1e-5f);
    }
    __syncthreads();
    for (int i = tid; i < 4096; i += 256) {
        int r = i >> 6, c = i & 63;
        sA[r * 65 + c] = (sA[r * 65 + c] - sMean[r]) * sRstd[r] * g1b[c] + be1b[c];
    }
    __syncthreads();
    // split-bf16 transposed write: element (b*64+c, d0+dd) = h2[dd][c]
    uint32_t* Ah = (uint32_t*)g_Ahi;
    uint32_t* Al = (uint32_t*)g_Alo;
    for (int i = tid; i < 2048; i += 256) {
        int c = i >> 5;
        int d2 = (i & 31) * 2;
        uint32_t hi, lo;
        split2(sA[d2 * 65 + c], sA[(d2 + 1) * 65 + c], hi, lo);
        size_t o = ((size_t)b * CTOK + c) * K2U32 + (d0 >> 1) + (d2 >> 1);
        Ah[o] = hi;
        Al[o] = lo;
    }
}

// ---------------------------------------------------------------------------
// K5/K7: split-bf16 mma.sync GEMM   C = relu(A @ W + bias)
//  A: split rows (Ahi/Alo [M][384] u32), B: transposed split (Bhi/Blo).
//  D += Ah*Bh + Ah*Bl + Al*Bh   (al*bl ~2^-18 dropped)
//  Block 128x128, k-tile 32 bf16, 2-stage cp.async, 8 warps of 64x32.
//  __launch_bounds__(256, 2): register-capped (<=128) so smem (80KB) admits
//  2 CTAs/SM — cross-CTA overlap hides sync drains and smem phases.
//  A-frags loaded per-mi (8 live regs) instead of all-up-front (32).
// ---------------------------------------------------------------------------
#define SSTRB 80                 // bytes per smem row (40 bf16)
#define TILEB (128 * SSTRB)      // 10240
#define STAGEB (4 * TILEB)       // 40960
#define GEMM_SMEM (2 * STAGEB)   // 81920
#define NKT 24                   // 768 / 32

__global__ __launch_bounds__(256, 2) void gemm_bf16s_kernel(
    const uint4* __restrict__ Ahi, const uint4* __restrict__ Alo,
    const uint4* __restrict__ Bhi, const uint4* __restrict__ Blo,
    const float* __restrict__ bias, float* __restrict__ C)
{
    extern __shared__ char smc[];
    const uint32_t sbase = smem_u32(smc);
    const int tid  = threadIdx.x;
    const int lane = tid & 31;
    const int wid  = tid >> 5;
    const int bx   = blockIdx.x;   // N tile (0..5)
    const int by   = blockIdx.y;   // M tile (0..511)

    const int warpM = (wid & 1) * 64;
    const int warpN = (wid >> 1) * 32;
    const int g  = lane >> 2;      // 0..7
    const int t4 = lane & 3;       // 0..3

    // loader mapping: 2 threads per row, each 2 uint4 of the 4 per (row, ktile)
    const int lrow = tid >> 1;            // 0..127
    const int ljj  = (tid & 1) * 2;       // 0 or 2
    const uint4* srcRow[4];
    srcRow[0] = Ahi + ((size_t)(by * 128) + lrow) * K2U4 + ljj;
    srcRow[1] = Alo + ((size_t)(by * 128) + lrow) * K2U4 + ljj;
    srcRow[2] = Bhi + ((size_t)(bx * 128) + lrow) * K2U4 + ljj;
    srcRow[3] = Blo + ((size_t)(bx * 128) + lrow) * K2U4 + ljj;
    const uint32_t ldst = lrow * SSTRB + ljj * 16;

    // ldmatrix per-lane address offset within an A tile (for a 16-row block)
    const uint32_t aoff = ((lane & 7) + ((lane >> 3) & 1) * 8) * SSTRB
                        + (lane >> 4) * 16;

    float acc[4][4][4];
    #pragma unroll
    for (int mi = 0; mi < 4; mi++)
        #pragma unroll
        for (int ni = 0; ni < 4; ni++)
            #pragma unroll
            for (int e = 0; e < 4; e++) acc[mi][ni][e] = 0.f;

    // preload stages 0, 1
    #pragma unroll
    for (int s = 0; s < 2; s++) {
        uint32_t sb = sbase + s * STAGEB + ldst;
        #pragma unroll
        for (int k = 0; k < 4; k++) {
            const uint4* sp = srcRow[k] + s * 4;
            cp16(sb + k * TILEB, sp);
            cp16(sb + k * TILEB + 16, sp + 1);
        }
        CP_COMMIT();
    }
    CP_WAIT(1);
    __syncthreads();

    for (int t = 0; t < NKT; t++) {
        const int s = t & 1;
        const uint32_t Ab  = sbase + s * STAGEB;
        const uint32_t Alb = Ab + TILEB;
        const uint32_t* Bh32 = (const uint32_t*)(smc + s * STAGEB + 2 * TILEB);
        const uint32_t* Bl32 = (const uint32_t*)(smc + s * STAGEB + 3 * TILEB);

        #pragma unroll
        for (int kk = 0; kk < 2; kk++) {
            // B frags for this k16 (reused across all mi) — 16 regs
            uint32_t bh[4][2], bl[4][2];
            #pragma unroll
            for (int ni = 0; ni < 4; ni++) {
                int n = warpN + ni * 8 + g;
                int o = n * 20 + kk * 8 + t4;    // 20 u32 per 80B row
                bh[ni][0] = Bh32[o];
                bh[ni][1] = Bh32[o + 4];
                bl[ni][0] = Bl32[o];
                bl[ni][1] = Bl32[o + 4];
            }
            // A frags per-mi (8 live regs): hh, hl, lh terms
            #pragma unroll
            for (int mi = 0; mi < 4; mi++) {
                uint32_t ro = (warpM + mi * 16) * SSTRB + aoff + kk * 32;
                uint32_t ah[4], al[4];
                ldsm_x4(ah, Ab + ro);
                ldsm_x4(al, Alb + ro);
                #pragma unroll
                for (int ni = 0; ni < 4; ni++)
                    mma_bf16(acc[mi][ni], ah, bh[ni][0], bh[ni][1]);
                #pragma unroll
                for (int ni = 0; ni < 4; ni++)
                    mma_bf16(acc[mi][ni], ah, bl[ni][0], bl[ni][1]);
                #pragma unroll
                for (int ni = 0; ni < 4; ni++)
                    mma_bf16(acc[mi][ni], al, bh[ni][0], bh[ni][1]);
            }
        }
        __syncthreads();
        if (t + 2 < NKT) {
            uint32_t sb = sbase + s * STAGEB + ldst;
            #pragma unroll
            for (int k = 0; k < 4; k++) {
                const uint4* sp = srcRow[k] + (t + 2) * 4;
                cp16(sb + k * TILEB, sp);
                cp16(sb + k * TILEB + 16, sp + 1);
            }
            CP_COMMIT();
            CP_WAIT(1);
        } else {
            CP_WAIT(0);
        }
        __syncthreads();
    }

    // epilogue: bias + relu
    #pragma unroll
    for (int mi = 0; mi < 4; mi++) {
        size_t row0 = (size_t)by * 128 + warpM + mi * 16 + g;
        #pragma unroll
        for (int ni = 0; ni < 4; ni++) {
            int col = bx * 128 + warpN + ni * 8 + t4 * 2;
            float b0 = bias[col], b1 = bias[col + 1];
            float2 v0, v1;
            v0.x = fmaxf(acc[mi][ni][0] + b0, 0.f);
            v0.y = fmaxf(acc[mi][ni][1] + b1, 0.f);
            v1.x = fmaxf(acc[mi][ni][2] + b0, 0.f);
            v1.y = fmaxf(acc[mi][ni][3] + b1, 0.f);
            *(float2*)&C[row0 * DDIM + col]       = v0;
            *(float2*)&C[(row0 + 8) * DDIM + col] = v1;
        }
    }
}

// ---------------------------------------------------------------------------
// K6: LayerNorm over 768 -> split-bf16 output (feeds next GEMM)
// ---------------------------------------------------------------------------
__global__ __launch_bounds__(256) void ln_rows_bf16_kernel(
    const float* __restrict__ in, uint32_t* __restrict__ outh,
    uint32_t* __restrict__ outl,
    const float* __restrict__ g, const float* __restrict__ be)
{
    size_t row = blockIdx.x;
    int tid = threadIdx.x;
    const float* p = in + row * DDIM;
    float v0 = p[tid], v1 = p[tid + 256], v2 = p[tid + 512];
    float s = v0 + v1 + v2;
    float sq = v0 * v0 + v1 * v1 + v2 * v2;
    __shared__ float sh[16];
    __shared__ float y[DDIM];
    #pragma unroll
    for (int o = 16; o; o >>= 1) {
        s  += __shfl_down_sync(0xffffffffu, s, o);
        sq += __shfl_down_sync(0xffffffffu, sq, o);
    }
    if ((tid & 31) == 0) { sh[tid >> 5] = s; sh[8 + (tid >> 5)] = sq; }
    __syncthreads();
    if (tid < 32) {
        float a = (tid < 8) ? sh[tid] : 0.f;
        float c = (tid < 8) ? sh[8 + tid] : 0.f;
        #pragma unroll
        for (int o = 4; o; o >>= 1) {
            a += __shfl_down_sync(0xffffffffu, a, o);
            c += __shfl_down_sync(0xffffffffu, c, o);
        }
        if (tid == 0) { sh[0] = a; sh[1] = c; }
    }
    __syncthreads();
    float mean = sh[0] * (1.f / DDIM);
    float var  = sh[1] * (1.f / DDIM) - mean * mean;
    float rstd = rsqrtf(fmaxf(var, 0.f) + 1e-5f);
    y[tid]       = (v0 - mean) * rstd * g[tid]       + be[tid];
    y[tid + 256] = (v1 - mean) * rstd * g[tid + 256] + be[tid + 256];
    y[tid + 512] = (v2 - mean) * rstd * g[tid + 512] + be[tid + 512];
    __syncthreads();
    #pragma unroll
    for (int q = 0; q < 2; q++) {
        int pr = tid + q * 256;
        if (pr < K2U32) {
            uint32_t hi, lo;
            split2(y[2 * pr], y[2 * pr + 1], hi, lo);
            outh[row * K2U32 + pr] = hi;
            outl[row * K2U32 + pr] = lo;
        }
    }
}

// ---------------------------------------------------------------------------
// K8: final LayerNorm -> fp32 out
// ---------------------------------------------------------------------------
__global__ __launch_bounds__(256) void ln_rows_kernel(
    const float* __restrict__ in, float* __restrict__ out,
    const float* __restrict__ g, const float* __restrict__ be)
{
    size_t row = blockIdx.x;
    int tid = threadIdx.x;
    const float* p = in + row * DDIM;
    float* q = out + row * DDIM;
    float v0 = p[tid], v1 = p[tid + 256], v2 = p[tid + 512];
    float s = v0 + v1 + v2;
    float sq = v0 * v0 + v1 * v1 + v2 * v2;
    __shared__ float sh[16];
    #pragma unroll
    for (int o = 16; o; o >>= 1) {
        s  += __shfl_down_sync(0xffffffffu, s, o);
        sq += __shfl_down_sync(0xffffffffu, sq, o);
    }
    if ((tid & 31) == 0) { sh[tid >> 5] = s; sh[8 + (tid >> 5)] = sq; }
    __syncthreads();
    if (tid < 32) {
        float a = (tid < 8) ? sh[tid] : 0.f;
        float c = (tid < 8) ? sh[8 + tid] : 0.f;
        #pragma unroll
        for (int o = 4; o; o >>= 1) {
            a += __shfl_down_sync(0xffffffffu, a, o);
            c += __shfl_down_sync(0xffffffffu, c, o);
        }
        if (tid == 0) { sh[0] = a; sh[1] = c; }
    }
    __syncthreads();
    float mean = sh[0] * (1.f / DDIM);
    float var  = sh[1] * (1.f / DDIM) - mean * mean;
    float rstd = rsqrtf(fmaxf(var, 0.f) + 1e-5f);
    q[tid]       = (v0 - mean) * rstd * g[tid]       + be[tid];
    q[tid + 256] = (v1 - mean) * rstd * g[tid + 256] + be[tid + 256];
    q[tid + 512] = (v2 - mean) * rstd * g[tid + 512] + be[tid + 512];
}

// ---------------------------------------------------------------------------
// Launch
// ---------------------------------------------------------------------------
extern "C" void kernel_launch(void* const* d_in, const int* in_sizes, int n_in,
                              void* d_out, int out_size)
{
    const float* x_embed = (const float*)d_in[0];
    const float* prompt  = (const float*)d_in[1];
    const float* w1a  = (const float*)d_in[2];
    const float* b1a  = (const float*)d_in[3];
    const float* g1a  = (const float*)d_in[4];
    const float* be1a = (const float*)d_in[5];
    const float* w1b  = (const float*)d_in[6];
    const float* b1b  = (const float*)d_in[7];
    const float* g1b  = (const float*)d_in[8];
    const float* be1b = (const float*)d_in[9];
    const float* w2a  = (const float*)d_in[10];
    const float* b2a  = (const float*)d_in[11];
    const float* g2a  = (const float*)d_in[12];
    const float* be2a = (const float*)d_in[13];
    const float* w2b  = (const float*)d_in[14];
    const float* b2b  = (const float*)d_in[15];
    const float* g2b  = (const float*)d_in[16];
    const float* be2b = (const float*)d_in[17];
    float* out = (float*)d_out;

    int write_aux = (out_size >= OUT_TOTAL) ? 1 : 0;

    float* bufB = nullptr;
    uint4 *Ahi, *Alo, *Wahi, *Walo, *Wbhi, *Wblo;
    cudaGetSymbolAddress((void**)&bufB, g_bufB);
    cudaGetSymbolAddress((void**)&Ahi,  g_Ahi);
    cudaGetSymbolAddress((void**)&Alo,  g_Alo);
    cudaGetSymbolAddress((void**)&Wahi, g_Wahi);
    cudaGetSymbolAddress((void**)&Walo, g_Walo);
    cudaGetSymbolAddress((void**)&Wbhi, g_Wbhi);
    cudaGetSymbolAddress((void**)&Wblo, g_Wblo);

    // prompt selection pipeline
    pnorm_kernel<<<POOLN, 256>>>(prompt);
    xmean_norm_kernel<<<BDIM, 256>>>(x_embed);
    sim_topk_kernel<<<BDIM, 256>>>(out, write_aux);
    if (write_aux) reduce_rsim_kernel<<<1, 256>>>(out);

    // weight transpose+split
    wprep_kernel<<<dim3(24, 24), dim3(32, 8)>>>(w2a, (uint32_t*)Wahi, (uint32_t*)Walo);
    wprep_kernel<<<dim3(24, 24), dim3(32, 8)>>>(w2b, (uint32_t*)Wbhi, (uint32_t*)Wblo);

    // fused mlp_1 -> split-bf16 activations
    int mlp1_smem = 17088 * (int)sizeof(float);
    cudaFuncSetAttribute(mlp1_fused_kernel,
                         cudaFuncAttributeMaxDynamicSharedMemorySize, mlp1_smem);
    mlp1_fused_kernel<<<dim3(DDIM / 64, BDIM), 256, mlp1_smem>>>(
        x_embed, prompt, w1a, b1a, g1a, be1a, w1b, b1b, g1b, be1b);

    // mlp_2: split-bf16 mma GEMM + LN stages
    cudaFuncSetAttribute(gemm_bf16s_kernel,
                         cudaFuncAttributeMaxDynamicSharedMemorySize, GEMM_SMEM);
    dim3 ggrid(DDIM / 128, MROWS / 128);   // (6, 512)
    gemm_bf16s_kernel<<<ggrid, 256, GEMM_SMEM>>>(Ahi, Alo, Wahi, Walo, b2a, bufB);
    ln_rows_bf16_kernel<<<MROWS, 256>>>(bufB, (uint32_t*)Ahi, (uint32_t*)Alo, g2a, be2a);
    gemm_bf16s_kernel<<<ggrid, 256, GEMM_SMEM>>>(Ahi, Alo, Wbhi, Wblo, b2b, bufB);
    ln_rows_kernel<<<MROWS, 256>>>(bufB, out, g2b, be2b);
}

// round 9
// speedup vs baseline: 1.6721x; 1.5003x over previous
#include <cuda_runtime.h>
#include <cuda_fp16.h>
#include <cstdint>
#include <cstddef>

// ---------------------------------------------------------------------------
// Problem constants
// ---------------------------------------------------------------------------
#define BDIM 1024
#define SDIM 64
#define DDIM 768
#define POOLN 30
#define TOPK 4
#define SEQL 68          // TOPK + SDIM
#define CTOK 64
#define MROWS (BDIM*CTOK)    // 65536

#define OFF_RSIM (BDIM*CTOK*DDIM)               // 50331648
#define OFF_SIM  (OFF_RSIM + 1)                 // 50331649
#define OFF_IDX  (OFF_SIM + BDIM*POOLN)         // 50362369
#define OUT_TOTAL (OFF_IDX + BDIM*TOPK)         // 50366465

#define K2U32 384            // u32 per row of an fp16 matrix (768 fp16 / 2)
#define K2U4  96             // uint4 per row

// ---------------------------------------------------------------------------
// Scratch (static __device__ arrays — no runtime allocation)
// ---------------------------------------------------------------------------
__device__ float g_pnorm[POOLN * DDIM];
__device__ float g_xnorm[BDIM * DDIM];
__device__ int   g_idx[BDIM * TOPK];
__device__ float g_rsum[BDIM];
__device__ float g_bufB[(size_t)MROWS * DDIM];          // GEMM fp32 outputs
__device__ uint4 g_A16[(size_t)MROWS * K2U4];           // activation fp16
__device__ uint4 g_Wa16[DDIM * K2U4];                   // w2a^T fp16
__device__ uint4 g_Wb16[DDIM * K2U4];                   // w2b^T fp16

// ---------------------------------------------------------------------------
// helpers
// ---------------------------------------------------------------------------
__device__ __forceinline__ uint32_t smem_u32(const void* p) {
    uint32_t a;
    asm("{ .reg .u64 t; cvta.to.shared.u64 t, %1; cvt.u32.u64 %0, t; }"
        : "=r"(a) : "l"(p));
    return a;
}

__device__ __forceinline__ void ldsm_x4(uint32_t* r, uint32_t addr) {
    asm volatile("ldmatrix.sync.aligned.m8n8.x4.shared.b16 {%0,%1,%2,%3}, [%4];"
        : "=r"(r[0]), "=r"(r[1]), "=r"(r[2]), "=r"(r[3]) : "r"(addr));
}

__device__ __forceinline__ void mma_f16(float c[4], const uint32_t a[4],
                                        uint32_t b0, uint32_t b1) {
    asm volatile(
        "mma.sync.aligned.m16n8k16.row.col.f32.f16.f16.f32 "
        "{%0,%1,%2,%3}, {%4,%5,%6,%7}, {%8,%9}, {%0,%1,%2,%3};"
        : "+f"(c[0]), "+f"(c[1]), "+f"(c[2]), "+f"(c[3])
        : "r"(a[0]), "r"(a[1]), "r"(a[2]), "r"(a[3]), "r"(b0), "r"(b1));
}

__device__ __forceinline__ void cp16(uint32_t dst, const void* src) {
    asm volatile("cp.async.cg.shared.global [%0], [%1], 16;" :: "r"(dst), "l"(src));
}
#define CP_COMMIT() asm volatile("cp.async.commit_group;" ::: "memory")
#define CP_WAIT(n)  asm volatile("cp.async.wait_group %0;" :: "n"(n) : "memory")

// pack fp32 pair -> fp16x2
__device__ __forceinline__ uint32_t pack2h(float a, float b) {
    __half2 h = __floats2half2_rn(a, b);
    return *(uint32_t*)&h;
}

// ---------------------------------------------------------------------------
// K1: prompt_norm
// ---------------------------------------------------------------------------
__global__ __launch_bounds__(256) void pnorm_kernel(const float* __restrict__ prompt) {
    int p = blockIdx.x;
    int tid = threadIdx.x;
    const float* row = prompt + (size_t)p * DDIM;
    float v0 = row[tid], v1 = row[tid + 256], v2 = row[tid + 512];
    float ssq = v0 * v0 + v1 * v1 + v2 * v2;
    __shared__ float sh[8];
    #pragma unroll
    for (int o = 16; o; o >>= 1) ssq += __shfl_down_sync(0xffffffffu, ssq, o);
    if ((tid & 31) == 0) sh[tid >> 5] = ssq;
    __syncthreads();
    if (tid < 32) {
        float v = (tid < 8) ? sh[tid] : 0.f;
        #pragma unroll
        for (int o = 4; o; o >>= 1) v += __shfl_down_sync(0xffffffffu, v, o);
        if (tid == 0) sh[0] = v;
    }
    __syncthreads();
    float rn = rsqrtf(fmaxf(sh[0], 1e-12f));
    float* dst = g_pnorm + (size_t)p * DDIM;
    dst[tid]       = v0 * rn;
    dst[tid + 256] = v1 * rn;
    dst[tid + 512] = v2 * rn;
}

// ---------------------------------------------------------------------------
// K2: x_mean + l2 normalize
// ---------------------------------------------------------------------------
__global__ __launch_bounds__(256) void xmean_norm_kernel(const float* __restrict__ x) {
    int b = blockIdx.x;
    int tid = threadIdx.x;
    float m[3];
    float ssq = 0.f;
    #pragma unroll
    for (int i = 0; i < 3; i++) {
        int d = tid + i * 256;
        float s = 0.f;
        #pragma unroll 8
        for (int si = 0; si < SDIM; si++)
            s += x[((size_t)b * SDIM + si) * DDIM + d];
        m[i] = s * (1.f / SDIM);
        ssq += m[i] * m[i];
    }
    __shared__ float sh[8];
    #pragma unroll
    for (int o = 16; o; o >>= 1) ssq += __shfl_down_sync(0xffffffffu, ssq, o);
    if ((tid & 31) == 0) sh[tid >> 5] = ssq;
    __syncthreads();
    if (tid < 32) {
        float v = (tid < 8) ? sh[tid] : 0.f;
        #pragma unroll
        for (int o = 4; o; o >>= 1) v += __shfl_down_sync(0xffffffffu, v, o);
        if (tid == 0) sh[0] = v;
    }
    __syncthreads();
    float rn = rsqrtf(fmaxf(sh[0], 1e-12f));
    #pragma unroll
    for (int i = 0; i < 3; i++)
        g_xnorm[(size_t)b * DDIM + tid + i * 256] = m[i] * rn;
}

// ---------------------------------------------------------------------------
// K3: similarity + top-4 + per-batch reduce_sim partial
// ---------------------------------------------------------------------------
__global__ __launch_bounds__(256) void sim_topk_kernel(float* __restrict__ out, int write_aux) {
    int b = blockIdx.x;
    int tid = threadIdx.x;
    __shared__ float sx[DDIM];
    __shared__ float ssim[32];
    for (int i = tid; i < DDIM; i += 256) sx[i] = g_xnorm[(size_t)b * DDIM + i];
    __syncthreads();
    int p = tid >> 3;
    int l8 = tid & 7;
    float acc = 0.f;
    if (p < POOLN) {
        const float* pr = g_pnorm + (size_t)p * DDIM;
        for (int k = l8; k < DDIM; k += 8) acc += sx[k] * pr[k];
    }
    #pragma unroll
    for (int o = 4; o; o >>= 1) acc += __shfl_down_sync(0xffffffffu, acc, o, 8);
    if (l8 == 0 && p < POOLN) ssim[p] = acc;
    __syncthreads();
    if (write_aux && tid < POOLN) out[OFF_SIM + (size_t)b * POOLN + tid] = ssim[tid];
    if (tid == 0) {
        bool used[POOLN];
        #pragma unroll
        for (int i = 0; i < POOLN; i++) used[i] = false;
        float rs = 0.f;
        for (int k = 0; k < TOPK; k++) {
            int best = 0;
            float bv = -3.4e38f;
            for (int pp = 0; pp < POOLN; pp++) {
                if (!used[pp] && ssim[pp] > bv) { bv = ssim[pp]; best = pp; }
            }
            used[best] = true;
            g_idx[b * TOPK + k] = best;
            if (write_aux) out[OFF_IDX + (size_t)b * TOPK + k] = (float)best;
            rs += bv;
        }
        g_rsum[b] = rs;
    }
}

// ---------------------------------------------------------------------------
// K3b: reduce_sim scalar
// ---------------------------------------------------------------------------
__global__ __launch_bounds__(256) void reduce_rsim_kernel(float* __restrict__ out) {
    int tid = threadIdx.x;
    float v = g_rsum[tid] + g_rsum[tid + 256] + g_rsum[tid + 512] + g_rsum[tid + 768];
    __shared__ float sh[8];
    #pragma unroll
    for (int o = 16; o; o >>= 1) v += __shfl_down_sync(0xffffffffu, v, o);
    if ((tid & 31) == 0) sh[tid >> 5] = v;
    __syncthreads();
    if (tid < 32) {
        float w = (tid < 8) ? sh[tid] : 0.f;
        #pragma unroll
        for (int o = 4; o; o >>= 1) w += __shfl_down_sync(0xffffffffu, w, o);
        if (tid == 0) out[OFF_RSIM] = w * (1.f / BDIM);
    }
}

// ---------------------------------------------------------------------------
// K-wprep: transpose 768x768 weight into fp16 pairs.  grid (24,24), blk (32,8)
// out: Wt[n][k] packed fp16x2 along k.
// ---------------------------------------------------------------------------
__global__ __launch_bounds__(256) void wprep_kernel(
    const float* __restrict__ W, uint32_t* __restrict__ W16)
{
    __shared__ float t[32][33];
    int bxn = blockIdx.x;   // n tile
    int byk = blockIdx.y;   // k tile
    int tx = threadIdx.x, ty = threadIdx.y;
    #pragma unroll
    for (int i = 0; i < 4; i++) {
        int k = byk * 32 + ty + i * 8;
        t[ty + i * 8][tx] = W[(size_t)k * DDIM + bxn * 32 + tx];
    }
    __syncthreads();
    int tid = ty * 32 + tx;
    #pragma unroll
    for (int q = 0; q < 2; q++) {
        int idx = tid + q * 256;
        int nn = idx >> 4;         // 0..31
        int p  = idx & 15;         // k-pair within tile
        size_t o = (size_t)(bxn * 32 + nn) * K2U32 + byk * 16 + p;
        W16[o] = pack2h(t[2 * p][nn], t[2 * p + 1][nn]);
    }
}

// ---------------------------------------------------------------------------
// K4: fused mlp_1 (token mixing).  grid = (12, B), block=256.
// Output: fp16 activation rows into g_A16 (transposed to (b*64+c, d)).
// ---------------------------------------------------------------------------
__global__ __launch_bounds__(256) void mlp1_fused_kernel(
    const float* __restrict__ x_embed, const float* __restrict__ prompt,
    const float* __restrict__ w1a, const float* __restrict__ b1a,
    const float* __restrict__ g1a, const float* __restrict__ be1a,
    const float* __restrict__ w1b, const float* __restrict__ b1b,
    const float* __restrict__ g1b, const float* __restrict__ be1b)
{
    extern __shared__ float sm[];
    float* sW1a  = sm;              // 68*64 = 4352
    float* sW1b  = sm + 4352;       // 64*64 = 4096
    float* sA    = sm + 8448;       // 68*64 = 4352  (reused as H2, stride 65)
    float* sH    = sm + 12800;      // 64*65 = 4160
    float* sMean = sm + 16960;      // 64
    float* sRstd = sm + 17024;      // 64  -> total 17088 floats

    int b  = blockIdx.y;
    int d0 = blockIdx.x * 64;
    int tid = threadIdx.x;

    for (int i = tid; i < SEQL * 64; i += 256) sW1a[i] = w1a[i];
    for (int i = tid; i < 64 * 64;  i += 256) sW1b[i] = w1b[i];
    for (int i = tid; i < SEQL * 64; i += 256) {
        int s = i >> 6, dd = i & 63;
        float v;
        if (s < TOPK)
            v = prompt[(size_t)g_idx[b * TOPK + s] * DDIM + d0 + dd];
        else
            v = x_embed[((size_t)b * SDIM + (s - TOPK)) * DDIM + d0 + dd];
        sA[i] = v;
    }
    __syncthreads();

    int tx = tid & 15;
    int ty = tid >> 4;
    float acc[4][4];
    #pragma unroll
    for (int i = 0; i < 4; i++)
        #pragma unroll
        for (int j = 0; j < 4; j++) acc[i][j] = 0.f;

    #pragma unroll 4
    for (int s = 0; s < SEQL; s++) {
        float4 a4 = *(const float4*)&sA[s * 64 + ty * 4];
        float4 w4 = *(const float4*)&sW1a[s * 64 + tx * 4];
        float a[4] = {a4.x, a4.y, a4.z, a4.w};
        float w[4] = {w4.x, w4.y, w4.z, w4.w};
        #pragma unroll
        for (int i = 0; i < 4; i++)
            #pragma unroll
            for (int j = 0; j < 4; j++) acc[i][j] += a[i] * w[j];
    }
    #pragma unroll
    for (int i = 0; i < 4; i++) {
        int r = ty * 4 + i;
        #pragma unroll
        for (int j = 0; j < 4; j++) {
            int c = tx * 4 + j;
            sH[r * 65 + c] = fmaxf(acc[i][j] + b1a[c], 0.f);
        }
    }
    __syncthreads();
    if (tid < 64) {
        float s = 0.f, sq = 0.f;
        #pragma unroll 8
        for (int c = 0; c < 64; c++) { float v = sH[tid * 65 + c]; s += v; sq += v * v; }
        float m = s * (1.f / 64.f);
        float var = sq * (1.f / 64.f) - m * m;
        sMean[tid] = m;
        sRstd[tid] = rsqrtf(fmaxf(var, 0.f) + 1e-5f);
    }
    __syncthreads();
    for (int i = tid; i < 4096; i += 256) {
        int r = i >> 6, c = i & 63;
        sH[r * 65 + c] = (sH[r * 65 + c] - sMean[r]) * sRstd[r] * g1a[c] + be1a[c];
    }
    __syncthreads();

    #pragma unroll
    for (int i = 0; i < 4; i++)
        #pragma unroll
        for (int j = 0; j < 4; j++) acc[i][j] = 0.f;
    #pragma unroll 8
    for (int k = 0; k < 64; k++) {
        float a[4];
        #pragma unroll
        for (int i = 0; i < 4; i++) a[i] = sH[(ty * 4 + i) * 65 + k];
        float4 w4 = *(const float4*)&sW1b[k * 64 + tx * 4];
        float w[4] = {w4.x, w4.y, w4.z, w4.w};
        #pragma unroll
        for (int i = 0; i < 4; i++)
            #pragma unroll
            for (int j = 0; j < 4; j++) acc[i][j] += a[i] * w[j];
    }
    #pragma unroll
    for (int i = 0; i < 4; i++) {
        int r = ty * 4 + i;
        #pragma unroll
        for (int j = 0; j < 4; j++) {
            int c = tx * 4 + j;
            sA[r * 65 + c] = fmaxf(acc[i][j] + b1b[c], 0.f);
        }
    }
    __syncthreads();
    if (tid < 64) {
        float s = 0.f, sq = 0.f;
        #pragma unroll 8
        for (int c = 0; c < 64; c++) { float v = sA[tid * 65 + c]; s += v; sq += v * v; }
        float m = s * (1.f / 64.f);
        float var = sq * (1.f / 64.f) - m * m;
        sMean[tid] = m;
        sRstd[tid] = rsqrtf(fmaxf(var, 0.f) + 1e-5f);
    }
    __syncthreads();
    for (int i = tid; i < 4096; i += 256) {
        int r = i >> 6, c = i & 63;
        sA[r * 65 + c] = (sA[r * 65 + c] - sMean[r]) * sRstd[r] * g1b[c] + be1b[c];
    }
    __syncthreads();
    // fp16 transposed write: element (b*64+c, d0+dd) = h2[dd][c]
    uint32_t* A32 = (uint32_t*)g_A16;
    for (int i = tid; i < 2048; i += 256) {
        int c = i >> 5;
        int d2 = (i & 31) * 2;
        size_t o = ((size_t)b * CTOK + c) * K2U32 + (d0 >> 1) + (d2 >> 1);
        A32[o] = pack2h(sA[d2 * 65 + c], sA[(d2 + 1) * 65 + c]);
    }
}

// ---------------------------------------------------------------------------
// K5/K7: fp16 mma.sync GEMM   C = relu(A @ W + bias)
//  A: fp16 rows [M][384] u32, B: transposed fp16 (B[n][k] = W[k][n]).
//  Single-term fp16 (e5m10, 11 mantissa bits -> ~2.5e-4 rel err, under 1e-3).
//  Block 128x128, k-tile 32, 2-stage cp.async, 8 warps of 64x32,
//  2 CTAs/SM (smem 40KB/CTA, regs <=128).
// ---------------------------------------------------------------------------
#define SSTRB 80                 // bytes per smem row (40 fp16)
#define TILEB (128 * SSTRB)      // 10240
#define STAGEB (2 * TILEB)       // 20480  (A tile + B tile)
#define GEMM_SMEM (2 * STAGEB)   // 40960
#define NKT 24                   // 768 / 32

__global__ __launch_bounds__(256, 2) void gemm_f16_kernel(
    const uint4* __restrict__ A16, const uint4* __restrict__ B16,
    const float* __restrict__ bias, float* __restrict__ C)
{
    extern __shared__ char smc[];
    const uint32_t sbase = smem_u32(smc);
    const int tid  = threadIdx.x;
    const int lane = tid & 31;
    const int wid  = tid >> 5;
    const int bx   = blockIdx.x;   // N tile (0..5)
    const int by   = blockIdx.y;   // M tile (0..511)

    const int warpM = (wid & 1) * 64;
    const int warpN = (wid >> 1) * 32;
    const int g  = lane >> 2;      // 0..7
    const int t4 = lane & 3;       // 0..3

    // loader mapping: 2 threads per row, each 2 uint4 of the 4 per (row, ktile)
    const int lrow = tid >> 1;            // 0..127
    const int ljj  = (tid & 1) * 2;       // 0 or 2
    const uint4* srcA = A16 + ((size_t)(by * 128) + lrow) * K2U4 + ljj;
    const uint4* srcB = B16 + ((size_t)(bx * 128) + lrow) * K2U4 + ljj;
    const uint32_t ldst = lrow * SSTRB + ljj * 16;

    // ldmatrix per-lane address offset within an A tile (16-row block)
    const uint32_t aoff = ((lane & 7) + ((lane >> 3) & 1) * 8) * SSTRB
                        + (lane >> 4) * 16;

    float acc[4][4][4];
    #pragma unroll
    for (int mi = 0; mi < 4; mi++)
        #pragma unroll
        for (int ni = 0; ni < 4; ni++)
            #pragma unroll
            for (int e = 0; e < 4; e++) acc[mi][ni][e] = 0.f;

    // preload stages 0, 1
    #pragma unroll
    for (int s = 0; s < 2; s++) {
        uint32_t sb = sbase + s * STAGEB + ldst;
        const uint4* pa = srcA + s * 4;
        const uint4* pb = srcB + s * 4;
        cp16(sb, pa);
        cp16(sb + 16, pa + 1);
        cp16(sb + TILEB, pb);
        cp16(sb + TILEB + 16, pb + 1);
        CP_COMMIT();
    }
    CP_WAIT(1);
    __syncthreads();

    for (int t = 0; t < NKT; t++) {
        const int s = t & 1;
        const uint32_t Ab = sbase + s * STAGEB;
        const uint32_t* B32 = (const uint32_t*)(smc + s * STAGEB + TILEB);

        #pragma unroll
        for (int kk = 0; kk < 2; kk++) {
            // B frags for this k16 (reused across all mi) — 8 regs
            uint32_t bh[4][2];
            #pragma unroll
            for (int ni = 0; ni < 4; ni++) {
                int n = warpN + ni * 8 + g;
                int o = n * 20 + kk * 8 + t4;    // 20 u32 per 80B row
                bh[ni][0] = B32[o];
                bh[ni][1] = B32[o + 4];
            }
            #pragma unroll
            for (int mi = 0; mi < 4; mi++) {
                uint32_t ro = (warpM + mi * 16) * SSTRB + aoff + kk * 32;
                uint32_t ah[4];
                ldsm_x4(ah, Ab + ro);
                #pragma unroll
                for (int ni = 0; ni < 4; ni++)
                    mma_f16(acc[mi][ni], ah, bh[ni][0], bh[ni][1]);
            }
        }
        __syncthreads();
        if (t + 2 < NKT) {
            uint32_t sb = sbase + s * STAGEB + ldst;
            const uint4* pa = srcA + (t + 2) * 4;
            const uint4* pb = srcB + (t + 2) * 4;
            cp16(sb, pa);
            cp16(sb + 16, pa + 1);
            cp16(sb + TILEB, pb);
            cp16(sb + TILEB + 16, pb + 1);
            CP_COMMIT();
            CP_WAIT(1);
        } else {
            CP_WAIT(0);
        }
        __syncthreads();
    }

    // epilogue: bias + relu
    #pragma unroll
    for (int mi = 0; mi < 4; mi++) {
        size_t row0 = (size_t)by * 128 + warpM + mi * 16 + g;
        #pragma unroll
        for (int ni = 0; ni < 4; ni++) {
            int col = bx * 128 + warpN + ni * 8 + t4 * 2;
            float b0 = bias[col], b1 = bias[col + 1];
            float2 v0, v1;
            v0.x = fmaxf(acc[mi][ni][0] + b0, 0.f);
            v0.y = fmaxf(acc[mi][ni][1] + b1, 0.f);
            v1.x = fmaxf(acc[mi][ni][2] + b0, 0.f);
            v1.y = fmaxf(acc[mi][ni][3] + b1, 0.f);
            *(float2*)&C[row0 * DDIM + col]       = v0;
            *(float2*)&C[(row0 + 8) * DDIM + col] = v1;
        }
    }
}

// ---------------------------------------------------------------------------
// K6: LayerNorm over 768 -> fp16 output (feeds next GEMM)
// ---------------------------------------------------------------------------
__global__ __launch_bounds__(256) void ln_rows_f16_kernel(
    const float* __restrict__ in, uint32_t* __restrict__ out16,
    const float* __restrict__ g, const float* __restrict__ be)
{
    size_t row = blockIdx.x;
    int tid = threadIdx.x;
    const float* p = in + row * DDIM;
    float v0 = p[tid], v1 = p[tid + 256], v2 = p[tid + 512];
    float s = v0 + v1 + v2;
    float sq = v0 * v0 + v1 * v1 + v2 * v2;
    __shared__ float sh[16];
    __shared__ float y[DDIM];
    #pragma unroll
    for (int o = 16; o; o >>= 1) {
        s  += __shfl_down_sync(0xffffffffu, s, o);
        sq += __shfl_down_sync(0xffffffffu, sq, o);
    }
    if ((tid & 31) == 0) { sh[tid >> 5] = s; sh[8 + (tid >> 5)] = sq; }
    __syncthreads();
    if (tid < 32) {
        float a = (tid < 8) ? sh[tid] : 0.f;
        float c = (tid < 8) ? sh[8 + tid] : 0.f;
        #pragma unroll
        for (int o = 4; o; o >>= 1) {
            a += __shfl_down_sync(0xffffffffu, a, o);
            c += __shfl_down_sync(0xffffffffu, c, o);
        }
        if (tid == 0) { sh[0] = a; sh[1] = c; }
    }
    __syncthreads();
    float mean = sh[0] * (1.f / DDIM);
    float var  = sh[1] * (1.f / DDIM) - mean * mean;
    float rstd = rsqrtf(fmaxf(var, 0.f) + 1e-5f);
    y[tid]       = (v0 - mean) * rstd * g[tid]       + be[tid];
    y[tid + 256] = (v1 - mean) * rstd * g[tid + 256] + be[tid + 256];
    y[tid + 512] = (v2 - mean) * rstd * g[tid + 512] + be[tid + 512];
    __syncthreads();
    #pragma unroll
    for (int q = 0; q < 2; q++) {
        int pr = tid + q * 256;
        if (pr < K2U32)
            out16[row * K2U32 + pr] = pack2h(y[2 * pr], y[2 * pr + 1]);
    }
}

// ---------------------------------------------------------------------------
// K8: final LayerNorm -> fp32 out
// ---------------------------------------------------------------------------
__global__ __launch_bounds__(256) void ln_rows_kernel(
    const float* __restrict__ in, float* __restrict__ out,
    const float* __restrict__ g, const float* __restrict__ be)
{
    size_t row = blockIdx.x;
    int tid = threadIdx.x;
    const float* p = in + row * DDIM;
    float* q = out + row * DDIM;
    float v0 = p[tid], v1 = p[tid + 256], v2 = p[tid + 512];
    float s = v0 + v1 + v2;
    float sq = v0 * v0 + v1 * v1 + v2 * v2;
    __shared__ float sh[16];
    #pragma unroll
    for (int o = 16; o; o >>= 1) {
        s  += __shfl_down_sync(0xffffffffu, s, o);
        sq += __shfl_down_sync(0xffffffffu, sq, o);
    }
    if ((tid & 31) == 0) { sh[tid >> 5] = s; sh[8 + (tid >> 5)] = sq; }
    __syncthreads();
    if (tid < 32) {
        float a = (tid < 8) ? sh[tid] : 0.f;
        float c = (tid < 8) ? sh[8 + tid] : 0.f;
        #pragma unroll
        for (int o = 4; o; o >>= 1) {
            a += __shfl_down_sync(0xffffffffu, a, o);
            c += __shfl_down_sync(0xffffffffu, c, o);
        }
        if (tid == 0) { sh[0] = a; sh[1] = c; }
    }
    __syncthreads();
    float mean = sh[0] * (1.f / DDIM);
    float var  = sh[1] * (1.f / DDIM) - mean * mean;
    float rstd = rsqrtf(fmaxf(var, 0.f) + 1e-5f);
    q[tid]       = (v0 - mean) * rstd * g[tid]       + be[tid];
    q[tid + 256] = (v1 - mean) * rstd * g[tid + 256] + be[tid + 256];
    q[tid + 512] = (v2 - mean) * rstd * g[tid + 512] + be[tid + 512];
}

// ---------------------------------------------------------------------------
// Launch
// ---------------------------------------------------------------------------
extern "C" void kernel_launch(void* const* d_in, const int* in_sizes, int n_in,
                              void* d_out, int out_size)
{
    const float* x_embed = (const float*)d_in[0];
    const float* prompt  = (const float*)d_in[1];
    const float* w1a  = (const float*)d_in[2];
    const float* b1a  = (const float*)d_in[3];
    const float* g1a  = (const float*)d_in[4];
    const float* be1a = (const float*)d_in[5];
    const float* w1b  = (const float*)d_in[6];
    const float* b1b  = (const float*)d_in[7];
    const float* g1b  = (const float*)d_in[8];
    const float* be1b = (const float*)d_in[9];
    const float* w2a  = (const float*)d_in[10];
    const float* b2a  = (const float*)d_in[11];
    const float* g2a  = (const float*)d_in[12];
    const float* be2a = (const float*)d_in[13];
    const float* w2b  = (const float*)d_in[14];
    const float* b2b  = (const float*)d_in[15];
    const float* g2b  = (const float*)d_in[16];
    const float* be2b = (const float*)d_in[17];
    float* out = (float*)d_out;

    int write_aux = (out_size >= OUT_TOTAL) ? 1 : 0;

    float* bufB = nullptr;
    uint4 *A16, *Wa16, *Wb16;
    cudaGetSymbolAddress((void**)&bufB, g_bufB);
    cudaGetSymbolAddress((void**)&A16,  g_A16);
    cudaGetSymbolAddress((void**)&Wa16, g_Wa16);
    cudaGetSymbolAddress((void**)&Wb16, g_Wb16);

    // prompt selection pipeline
    pnorm_kernel<<<POOLN, 256>>>(prompt);
    xmean_norm_kernel<<<BDIM, 256>>>(x_embed);
    sim_topk_kernel<<<BDIM, 256>>>(out, write_aux);
    if (write_aux) reduce_rsim_kernel<<<1, 256>>>(out);

    // weight transpose -> fp16
    wprep_kernel<<<dim3(24, 24), dim3(32, 8)>>>(w2a, (uint32_t*)Wa16);
    wprep_kernel<<<dim3(24, 24), dim3(32, 8)>>>(w2b, (uint32_t*)Wb16);

    // fused mlp_1 -> fp16 activations
    int mlp1_smem = 17088 * (int)sizeof(float);
    cudaFuncSetAttribute(mlp1_fused_kernel,
                         cudaFuncAttributeMaxDynamicSharedMemorySize, mlp1_smem);
    mlp1_fused_kernel<<<dim3(DDIM / 64, BDIM), 256, mlp1_smem>>>(
        x_embed, prompt, w1a, b1a, g1a, be1a, w1b, b1b, g1b, be1b);

    // mlp_2: fp16 mma GEMM + LN stages
    cudaFuncSetAttribute(gemm_f16_kernel,
                         cudaFuncAttributeMaxDynamicSharedMemorySize, GEMM_SMEM);
    dim3 ggrid(DDIM / 128, MROWS / 128);   // (6, 512)
    gemm_f16_kernel<<<ggrid, 256, GEMM_SMEM>>>(A16, Wa16, b2a, bufB);
    ln_rows_f16_kernel<<<MROWS, 256>>>(bufB, (uint32_t*)A16, g2a, be2a);
    gemm_f16_kernel<<<ggrid, 256, GEMM_SMEM>>>(A16, Wb16, b2b, bufB);
    ln_rows_kernel<<<MROWS, 256>>>(bufB, out, g2b, be2b);
}

// round 10
// speedup vs baseline: 1.8023x; 1.0779x over previous
#include <cuda_runtime.h>
#include <cuda_fp16.h>
#include <cstdint>
#include <cstddef>

// ---------------------------------------------------------------------------
// Problem constants
// ---------------------------------------------------------------------------
#define BDIM 1024
#define SDIM 64
#define DDIM 768
#define POOLN 30
#define TOPK 4
#define SEQL 68          // TOPK + SDIM
#define CTOK 64
#define MROWS (BDIM*CTOK)    // 65536

#define OFF_RSIM (BDIM*CTOK*DDIM)               // 50331648
#define OFF_SIM  (OFF_RSIM + 1)                 // 50331649
#define OFF_IDX  (OFF_SIM + BDIM*POOLN)         // 50362369
#define OUT_TOTAL (OFF_IDX + BDIM*TOPK)         // 50366465

#define K2U32 384            // u32 per row of an fp16 matrix (768 fp16 / 2)
#define K2U4  96             // uint4 per row

// ---------------------------------------------------------------------------
// Scratch (static __device__ arrays — no runtime allocation)
// ---------------------------------------------------------------------------
__device__ float g_pnorm[POOLN * DDIM];
__device__ float g_xnorm[BDIM * DDIM];
__device__ int   g_idx[BDIM * TOPK];
__device__ float g_rsum[BDIM];
__device__ float g_bufB[(size_t)MROWS * DDIM];          // GEMM fp32 outputs
__device__ uint4 g_A16[(size_t)MROWS * K2U4];           // activation fp16
__device__ uint4 g_Wa16[DDIM * K2U4];                   // w2a^T fp16
__device__ uint4 g_Wb16[DDIM * K2U4];                   // w2b^T fp16

// ---------------------------------------------------------------------------
// helpers
// ---------------------------------------------------------------------------
__device__ __forceinline__ uint32_t smem_u32(const void* p) {
    uint32_t a;
    asm("{ .reg .u64 t; cvta.to.shared.u64 t, %1; cvt.u32.u64 %0, t; }"
        : "=r"(a) : "l"(p));
    return a;
}

__device__ __forceinline__ void ldsm_x4(uint32_t* r, uint32_t addr) {
    asm volatile("ldmatrix.sync.aligned.m8n8.x4.shared.b16 {%0,%1,%2,%3}, [%4];"
        : "=r"(r[0]), "=r"(r[1]), "=r"(r[2]), "=r"(r[3]) : "r"(addr));
}

__device__ __forceinline__ void mma_f16(float c[4], const uint32_t a[4],
                                        uint32_t b0, uint32_t b1) {
    asm volatile(
        "mma.sync.aligned.m16n8k16.row.col.f32.f16.f16.f32 "
        "{%0,%1,%2,%3}, {%4,%5,%6,%7}, {%8,%9}, {%0,%1,%2,%3};"
        : "+f"(c[0]), "+f"(c[1]), "+f"(c[2]), "+f"(c[3])
        : "r"(a[0]), "r"(a[1]), "r"(a[2]), "r"(a[3]), "r"(b0), "r"(b1));
}

__device__ __forceinline__ void cp16(uint32_t dst, const void* src) {
    asm volatile("cp.async.cg.shared.global [%0], [%1], 16;" :: "r"(dst), "l"(src));
}
#define CP_COMMIT() asm volatile("cp.async.commit_group;" ::: "memory")
#define CP_WAIT(n)  asm volatile("cp.async.wait_group %0;" :: "n"(n) : "memory")

// pack fp32 pair -> fp16x2
__device__ __forceinline__ uint32_t pack2h(float a, float b) {
    __half2 h = __floats2half2_rn(a, b);
    return *(uint32_t*)&h;
}

// ---------------------------------------------------------------------------
// K1: prompt_norm
// ---------------------------------------------------------------------------
__global__ __launch_bounds__(256) void pnorm_kernel(const float* __restrict__ prompt) {
    int p = blockIdx.x;
    int tid = threadIdx.x;
    const float* row = prompt + (size_t)p * DDIM;
    float v0 = row[tid], v1 = row[tid + 256], v2 = row[tid + 512];
    float ssq = v0 * v0 + v1 * v1 + v2 * v2;
    __shared__ float sh[8];
    #pragma unroll
    for (int o = 16; o; o >>= 1) ssq += __shfl_down_sync(0xffffffffu, ssq, o);
    if ((tid & 31) == 0) sh[tid >> 5] = ssq;
    __syncthreads();
    if (tid < 32) {
        float v = (tid < 8) ? sh[tid] : 0.f;
        #pragma unroll
        for (int o = 4; o; o >>= 1) v += __shfl_down_sync(0xffffffffu, v, o);
        if (tid == 0) sh[0] = v;
    }
    __syncthreads();
    float rn = rsqrtf(fmaxf(sh[0], 1e-12f));
    float* dst = g_pnorm + (size_t)p * DDIM;
    dst[tid]       = v0 * rn;
    dst[tid + 256] = v1 * rn;
    dst[tid + 512] = v2 * rn;
}

// ---------------------------------------------------------------------------
// K2: x_mean + l2 normalize
// ---------------------------------------------------------------------------
__global__ __launch_bounds__(256) void xmean_norm_kernel(const float* __restrict__ x) {
    int b = blockIdx.x;
    int tid = threadIdx.x;
    float m[3];
    float ssq = 0.f;
    #pragma unroll
    for (int i = 0; i < 3; i++) {
        int d = tid + i * 256;
        float s = 0.f;
        #pragma unroll 8
        for (int si = 0; si < SDIM; si++)
            s += x[((size_t)b * SDIM + si) * DDIM + d];
        m[i] = s * (1.f / SDIM);
        ssq += m[i] * m[i];
    }
    __shared__ float sh[8];
    #pragma unroll
    for (int o = 16; o; o >>= 1) ssq += __shfl_down_sync(0xffffffffu, ssq, o);
    if ((tid & 31) == 0) sh[tid >> 5] = ssq;
    __syncthreads();
    if (tid < 32) {
        float v = (tid < 8) ? sh[tid] : 0.f;
        #pragma unroll
        for (int o = 4; o; o >>= 1) v += __shfl_down_sync(0xffffffffu, v, o);
        if (tid == 0) sh[0] = v;
    }
    __syncthreads();
    float rn = rsqrtf(fmaxf(sh[0], 1e-12f));
    #pragma unroll
    for (int i = 0; i < 3; i++)
        g_xnorm[(size_t)b * DDIM + tid + i * 256] = m[i] * rn;
}

// ---------------------------------------------------------------------------
// K3: similarity + top-4 + per-batch reduce_sim partial
// ---------------------------------------------------------------------------
__global__ __launch_bounds__(256) void sim_topk_kernel(float* __restrict__ out, int write_aux) {
    int b = blockIdx.x;
    int tid = threadIdx.x;
    __shared__ float sx[DDIM];
    __shared__ float ssim[32];
    for (int i = tid; i < DDIM; i += 256) sx[i] = g_xnorm[(size_t)b * DDIM + i];
    __syncthreads();
    int p = tid >> 3;
    int l8 = tid & 7;
    float acc = 0.f;
    if (p < POOLN) {
        const float* pr = g_pnorm + (size_t)p * DDIM;
        for (int k = l8; k < DDIM; k += 8) acc += sx[k] * pr[k];
    }
    #pragma unroll
    for (int o = 4; o; o >>= 1) acc += __shfl_down_sync(0xffffffffu, acc, o, 8);
    if (l8 == 0 && p < POOLN) ssim[p] = acc;
    __syncthreads();
    if (write_aux && tid < POOLN) out[OFF_SIM + (size_t)b * POOLN + tid] = ssim[tid];
    if (tid == 0) {
        bool used[POOLN];
        #pragma unroll
        for (int i = 0; i < POOLN; i++) used[i] = false;
        float rs = 0.f;
        for (int k = 0; k < TOPK; k++) {
            int best = 0;
            float bv = -3.4e38f;
            for (int pp = 0; pp < POOLN; pp++) {
                if (!used[pp] && ssim[pp] > bv) { bv = ssim[pp]; best = pp; }
            }
            used[best] = true;
            g_idx[b * TOPK + k] = best;
            if (write_aux) out[OFF_IDX + (size_t)b * TOPK + k] = (float)best;
            rs += bv;
        }
        g_rsum[b] = rs;
    }
}

// ---------------------------------------------------------------------------
// K3b: reduce_sim scalar
// ---------------------------------------------------------------------------
__global__ __launch_bounds__(256) void reduce_rsim_kernel(float* __restrict__ out) {
    int tid = threadIdx.x;
    float v = g_rsum[tid] + g_rsum[tid + 256] + g_rsum[tid + 512] + g_rsum[tid + 768];
    __shared__ float sh[8];
    #pragma unroll
    for (int o = 16; o; o >>= 1) v += __shfl_down_sync(0xffffffffu, v, o);
    if ((tid & 31) == 0) sh[tid >> 5] = v;
    __syncthreads();
    if (tid < 32) {
        float w = (tid < 8) ? sh[tid] : 0.f;
        #pragma unroll
        for (int o = 4; o; o >>= 1) w += __shfl_down_sync(0xffffffffu, w, o);
        if (tid == 0) out[OFF_RSIM] = w * (1.f / BDIM);
    }
}

// ---------------------------------------------------------------------------
// K-wprep: transpose 768x768 weight into fp16 pairs.  grid (24,24), blk (32,8)
// ---------------------------------------------------------------------------
__global__ __launch_bounds__(256) void wprep_kernel(
    const float* __restrict__ W, uint32_t* __restrict__ W16)
{
    __shared__ float t[32][33];
    int bxn = blockIdx.x;   // n tile
    int byk = blockIdx.y;   // k tile
    int tx = threadIdx.x, ty = threadIdx.y;
    #pragma unroll
    for (int i = 0; i < 4; i++) {
        int k = byk * 32 + ty + i * 8;
        t[ty + i * 8][tx] = W[(size_t)k * DDIM + bxn * 32 + tx];
    }
    __syncthreads();
    int tid = ty * 32 + tx;
    #pragma unroll
    for (int q = 0; q < 2; q++) {
        int idx = tid + q * 256;
        int nn = idx >> 4;         // 0..31
        int p  = idx & 15;         // k-pair within tile
        size_t o = (size_t)(bxn * 32 + nn) * K2U32 + byk * 16 + p;
        W16[o] = pack2h(t[2 * p][nn], t[2 * p + 1][nn]);
    }
}

// ---------------------------------------------------------------------------
// K4: fused mlp_1 (token mixing).  grid = (12, B), block=256.
// Output: fp16 activation rows into g_A16 (transposed to (b*64+c, d)).
// LN stats computed 4-threads-per-row with shfl reduction (was 64 serial).
// ---------------------------------------------------------------------------
__global__ __launch_bounds__(256) void mlp1_fused_kernel(
    const float* __restrict__ x_embed, const float* __restrict__ prompt,
    const float* __restrict__ w1a, const float* __restrict__ b1a,
    const float* __restrict__ g1a, const float* __restrict__ be1a,
    const float* __restrict__ w1b, const float* __restrict__ b1b,
    const float* __restrict__ g1b, const float* __restrict__ be1b)
{
    extern __shared__ float sm[];
    float* sW1a  = sm;              // 68*64 = 4352
    float* sW1b  = sm + 4352;       // 64*64 = 4096
    float* sA    = sm + 8448;       // 68*64 = 4352  (reused as H2, stride 65)
    float* sH    = sm + 12800;      // 64*65 = 4160
    float* sMean = sm + 16960;      // 64
    float* sRstd = sm + 17024;      // 64  -> total 17088 floats

    int b  = blockIdx.y;
    int d0 = blockIdx.x * 64;
    int tid = threadIdx.x;

    for (int i = tid; i < SEQL * 64; i += 256) sW1a[i] = w1a[i];
    for (int i = tid; i < 64 * 64;  i += 256) sW1b[i] = w1b[i];
    for (int i = tid; i < SEQL * 64; i += 256) {
        int s = i >> 6, dd = i & 63;
        float v;
        if (s < TOPK)
            v = prompt[(size_t)g_idx[b * TOPK + s] * DDIM + d0 + dd];
        else
            v = x_embed[((size_t)b * SDIM + (s - TOPK)) * DDIM + d0 + dd];
        sA[i] = v;
    }
    __syncthreads();

    int tx = tid & 15;
    int ty = tid >> 4;
    float acc[4][4];
    #pragma unroll
    for (int i = 0; i < 4; i++)
        #pragma unroll
        for (int j = 0; j < 4; j++) acc[i][j] = 0.f;

    #pragma unroll 4
    for (int s = 0; s < SEQL; s++) {
        float4 a4 = *(const float4*)&sA[s * 64 + ty * 4];
        float4 w4 = *(const float4*)&sW1a[s * 64 + tx * 4];
        float a[4] = {a4.x, a4.y, a4.z, a4.w};
        float w[4] = {w4.x, w4.y, w4.z, w4.w};
        #pragma unroll
        for (int i = 0; i < 4; i++)
            #pragma unroll
            for (int j = 0; j < 4; j++) acc[i][j] += a[i] * w[j];
    }
    #pragma unroll
    for (int i = 0; i < 4; i++) {
        int r = ty * 4 + i;
        #pragma unroll
        for (int j = 0; j < 4; j++) {
            int c = tx * 4 + j;
            sH[r * 65 + c] = fmaxf(acc[i][j] + b1a[c], 0.f);
        }
    }
    __syncthreads();
    // LN stats: 4 threads per row
    {
        int r = tid >> 2, q = tid & 3;
        float s_ = 0.f, sq_ = 0.f;
        #pragma unroll
        for (int j = 0; j < 16; j++) {
            float v = sH[r * 65 + q * 16 + j];
            s_ += v; sq_ += v * v;
        }
        s_  += __shfl_xor_sync(0xffffffffu, s_, 1);
        sq_ += __shfl_xor_sync(0xffffffffu, sq_, 1);
        s_  += __shfl_xor_sync(0xffffffffu, s_, 2);
        sq_ += __shfl_xor_sync(0xffffffffu, sq_, 2);
        if (q == 0) {
            float m = s_ * (1.f / 64.f);
            float var = sq_ * (1.f / 64.f) - m * m;
            sMean[r] = m;
            sRstd[r] = rsqrtf(fmaxf(var, 0.f) + 1e-5f);
        }
    }
    __syncthreads();
    for (int i = tid; i < 4096; i += 256) {
        int r = i >> 6, c = i & 63;
        sH[r * 65 + c] = (sH[r * 65 + c] - sMean[r]) * sRstd[r] * g1a[c] + be1a[c];
    }
    __syncthreads();

    #pragma unroll
    for (int i = 0; i < 4; i++)
        #pragma unroll
        for (int j = 0; j < 4; j++) acc[i][j] = 0.f;
    #pragma unroll 8
    for (int k = 0; k < 64; k++) {
        float a[4];
        #pragma unroll
        for (int i = 0; i < 4; i++) a[i] = sH[(ty * 4 + i) * 65 + k];
        float4 w4 = *(const float4*)&sW1b[k * 64 + tx * 4];
        float w[4] = {w4.x, w4.y, w4.z, w4.w};
        #pragma unroll
        for (int i = 0; i < 4; i++)
            #pragma unroll
            for (int j = 0; j < 4; j++) acc[i][j] += a[i] * w[j];
    }
    #pragma unroll
    for (int i = 0; i < 4; i++) {
        int r = ty * 4 + i;
        #pragma unroll
        for (int j = 0; j < 4; j++) {
            int c = tx * 4 + j;
            sA[r * 65 + c] = fmaxf(acc[i][j] + b1b[c], 0.f);
        }
    }
    __syncthreads();
    {
        int r = tid >> 2, q = tid & 3;
        float s_ = 0.f, sq_ = 0.f;
        #pragma unroll
        for (int j = 0; j < 16; j++) {
            float v = sA[r * 65 + q * 16 + j];
            s_ += v; sq_ += v * v;
        }
        s_  += __shfl_xor_sync(0xffffffffu, s_, 1);
        sq_ += __shfl_xor_sync(0xffffffffu, sq_, 1);
        s_  += __shfl_xor_sync(0xffffffffu, s_, 2);
        sq_ += __shfl_xor_sync(0xffffffffu, sq_, 2);
        if (q == 0) {
            float m = s_ * (1.f / 64.f);
            float var = sq_ * (1.f / 64.f) - m * m;
            sMean[r] = m;
            sRstd[r] = rsqrtf(fmaxf(var, 0.f) + 1e-5f);
        }
    }
    __syncthreads();
    for (int i = tid; i < 4096; i += 256) {
        int r = i >> 6, c = i & 63;
        sA[r * 65 + c] = (sA[r * 65 + c] - sMean[r]) * sRstd[r] * g1b[c] + be1b[c];
    }
    __syncthreads();
    // fp16 transposed write: element (b*64+c, d0+dd) = h2[dd][c]
    uint32_t* A32 = (uint32_t*)g_A16;
    for (int i = tid; i < 2048; i += 256) {
        int c = i >> 5;
        int d2 = (i & 31) * 2;
        size_t o = ((size_t)b * CTOK + c) * K2U32 + (d0 >> 1) + (d2 >> 1);
        A32[o] = pack2h(sA[d2 * 65 + c], sA[(d2 + 1) * 65 + c]);
    }
}

// ---------------------------------------------------------------------------
// K5/K7: fp16 mma.sync GEMM   C = relu(A @ W + bias)
//  4-stage cp.async pipeline, ONE __syncthreads per k-tile (always-commit).
//  B-fragments via ldmatrix.x4 over n-major rows (B^T row-major == B col-major
//  fragment).  Block 128x128, k-tile 32, 8 warps of 64x32, 2 CTAs/SM.
// ---------------------------------------------------------------------------
#define SSTRB 80                 // bytes per smem row (40 fp16)
#define TILEB (128 * SSTRB)      // 10240
#define STAGEB (2 * TILEB)       // 20480  (A tile + B tile)
#define NSTAGE 4
#define GEMM_SMEM (NSTAGE * STAGEB)   // 81920
#define NKT 24                   // 768 / 32

__global__ __launch_bounds__(256, 2) void gemm_f16_kernel(
    const uint4* __restrict__ A16, const uint4* __restrict__ B16,
    const float* __restrict__ bias, float* __restrict__ C)
{
    extern __shared__ char smc[];
    const uint32_t sbase = smem_u32(smc);
    const int tid  = threadIdx.x;
    const int lane = tid & 31;
    const int wid  = tid >> 5;
    const int bx   = blockIdx.x;   // N tile (0..5)
    const int by   = blockIdx.y;   // M tile (0..511)

    const int warpM = (wid & 1) * 64;
    const int warpN = (wid >> 1) * 32;
    const int g  = lane >> 2;      // 0..7
    const int t4 = lane & 3;       // 0..3

    // loader mapping: 2 threads per row, each 2 uint4 of the 4 per (row, ktile)
    const int lrow = tid >> 1;            // 0..127
    const int ljj  = (tid & 1) * 2;       // 0 or 2
    const uint4* srcA = A16 + ((size_t)(by * 128) + lrow) * K2U4 + ljj;
    const uint4* srcB = B16 + ((size_t)(bx * 128) + lrow) * K2U4 + ljj;
    const uint32_t ldst = lrow * SSTRB + ljj * 16;

    // ldmatrix per-lane address offsets
    const uint32_t aoff = ((lane & 7) + ((lane >> 3) & 1) * 8) * SSTRB
                        + (lane >> 4) * 16;                       // A (16-row blk)
    const uint32_t boff = (warpN + (lane & 7)) * SSTRB
                        + (lane >> 3) * 16;                       // B (x4: k0..31)

    float acc[4][4][4];
    #pragma unroll
    for (int mi = 0; mi < 4; mi++)
        #pragma unroll
        for (int ni = 0; ni < 4; ni++)
            #pragma unroll
            for (int e = 0; e < 4; e++) acc[mi][ni][e] = 0.f;

    // preload stages 0..2
    #pragma unroll
    for (int s = 0; s < NSTAGE - 1; s++) {
        uint32_t sb = sbase + s * STAGEB + ldst;
        const uint4* pa = srcA + s * 4;
        const uint4* pb = srcB + s * 4;
        cp16(sb, pa);
        cp16(sb + 16, pa + 1);
        cp16(sb + TILEB, pb);
        cp16(sb + TILEB + 16, pb + 1);
        CP_COMMIT();
    }

    for (int t = 0; t < NKT; t++) {
        CP_WAIT(2);            // stage t landed (2 newest groups are t+1, t+2)
        __syncthreads();       // all warps done with stage t-1's buffer too

        // issue loads for stage t+3 into buffer (t+3)%4 (freed by compute t-1)
        if (t + NSTAGE - 1 < NKT) {
            uint32_t sb = sbase + ((t + NSTAGE - 1) & (NSTAGE - 1)) * STAGEB + ldst;
            const uint4* pa = srcA + (t + NSTAGE - 1) * 4;
            const uint4* pb = srcB + (t + NSTAGE - 1) * 4;
            cp16(sb, pa);
            cp16(sb + 16, pa + 1);
            cp16(sb + TILEB, pb);
            cp16(sb + TILEB + 16, pb + 1);
        }
        CP_COMMIT();           // always commit (possibly empty group)

        // compute stage t
        const uint32_t Ab = sbase + (t & (NSTAGE - 1)) * STAGEB;
        const uint32_t Bb = Ab + TILEB;

        uint32_t bb[4][4];     // [ni][kk0.b0, kk0.b1, kk1.b0, kk1.b1]
        #pragma unroll
        for (int ni = 0; ni < 4; ni++)
            ldsm_x4(bb[ni], Bb + boff + ni * (8 * SSTRB));

        #pragma unroll
        for (int mi = 0; mi < 4; mi++) {
            uint32_t ro = (warpM + mi * 16) * SSTRB + aoff;
            uint32_t a0[4], a1[4];
            ldsm_x4(a0, Ab + ro);          // kk = 0
            ldsm_x4(a1, Ab + ro + 32);     // kk = 1
            #pragma unroll
            for (int ni = 0; ni < 4; ni++)
                mma_f16(acc[mi][ni], a0, bb[ni][0], bb[ni][1]);
            #pragma unroll
            for (int ni = 0; ni < 4; ni++)
                mma_f16(acc[mi][ni], a1, bb[ni][2], bb[ni][3]);
        }
    }

    // epilogue: bias + relu
    #pragma unroll
    for (int mi = 0; mi < 4; mi++) {
        size_t row0 = (size_t)by * 128 + warpM + mi * 16 + g;
        #pragma unroll
        for (int ni = 0; ni < 4; ni++) {
            int col = bx * 128 + warpN + ni * 8 + t4 * 2;
            float b0 = bias[col], b1 = bias[col + 1];
            float2 v0, v1;
            v0.x = fmaxf(acc[mi][ni][0] + b0, 0.f);
            v0.y = fmaxf(acc[mi][ni][1] + b1, 0.f);
            v1.x = fmaxf(acc[mi][ni][2] + b0, 0.f);
            v1.y = fmaxf(acc[mi][ni][3] + b1, 0.f);
            *(float2*)&C[row0 * DDIM + col]       = v0;
            *(float2*)&C[(row0 + 8) * DDIM + col] = v1;
        }
    }
}

// ---------------------------------------------------------------------------
// K6: LayerNorm over 768 -> fp16 output (feeds next GEMM)
// ---------------------------------------------------------------------------
__global__ __launch_bounds__(256) void ln_rows_f16_kernel(
    const float* __restrict__ in, uint32_t* __restrict__ out16,
    const float* __restrict__ g, const float* __restrict__ be)
{
    size_t row = blockIdx.x;
    int tid = threadIdx.x;
    const float* p = in + row * DDIM;
    float v0 = p[tid], v1 = p[tid + 256], v2 = p[tid + 512];
    float s = v0 + v1 + v2;
    float sq = v0 * v0 + v1 * v1 + v2 * v2;
    __shared__ float sh[16];
    __shared__ float y[DDIM];
    #pragma unroll
    for (int o = 16; o; o >>= 1) {
        s  += __shfl_down_sync(0xffffffffu, s, o);
        sq += __shfl_down_sync(0xffffffffu, sq, o);
    }
    if ((tid & 31) == 0) { sh[tid >> 5] = s; sh[8 + (tid >> 5)] = sq; }
    __syncthreads();
    if (tid < 32) {
        float a = (tid < 8) ? sh[tid] : 0.f;
        float c = (tid < 8) ? sh[8 + tid] : 0.f;
        #pragma unroll
        for (int o = 4; o; o >>= 1) {
            a += __shfl_down_sync(0xffffffffu, a, o);
            c += __shfl_down_sync(0xffffffffu, c, o);
        }
        if (tid == 0) { sh[0] = a; sh[1] = c; }
    }
    __syncthreads();
    float mean = sh[0] * (1.f / DDIM);
    float var  = sh[1] * (1.f / DDIM) - mean * mean;
    float rstd = rsqrtf(fmaxf(var, 0.f) + 1e-5f);
    y[tid]       = (v0 - mean) * rstd * g[tid]       + be[tid];
    y[tid + 256] = (v1 - mean) * rstd * g[tid + 256] + be[tid + 256];
    y[tid + 512] = (v2 - mean) * rstd * g[tid + 512] + be[tid + 512];
    __syncthreads();
    #pragma unroll
    for (int q = 0; q < 2; q++) {
        int pr = tid + q * 256;
        if (pr < K2U32)
            out16[row * K2U32 + pr] = pack2h(y[2 * pr], y[2 * pr + 1]);
    }
}

// ---------------------------------------------------------------------------
// K8: final LayerNorm -> fp32 out
// ---------------------------------------------------------------------------
__global__ __launch_bounds__(256) void ln_rows_kernel(
    const float* __restrict__ in, float* __restrict__ out,
    const float* __restrict__ g, const float* __restrict__ be)
{
    size_t row = blockIdx.x;
    int tid = threadIdx.x;
    const float* p = in + row * DDIM;
    float* q = out + row * DDIM;
    float v0 = p[tid], v1 = p[tid + 256], v2 = p[tid + 512];
    float s = v0 + v1 + v2;
    float sq = v0 * v0 + v1 * v1 + v2 * v2;
    __shared__ float sh[16];
    #pragma unroll
    for (int o = 16; o; o >>= 1) {
        s  += __shfl_down_sync(0xffffffffu, s, o);
        sq += __shfl_down_sync(0xffffffffu, sq, o);
    }
    if ((tid & 31) == 0) { sh[tid >> 5] = s; sh[8 + (tid >> 5)] = sq; }
    __syncthreads();
    if (tid < 32) {
        float a = (tid < 8) ? sh[tid] : 0.f;
        float c = (tid < 8) ? sh[8 + tid] : 0.f;
        #pragma unroll
        for (int o = 4; o; o >>= 1) {
            a += __shfl_down_sync(0xffffffffu, a, o);
            c += __shfl_down_sync(0xffffffffu, c, o);
        }
        if (tid == 0) { sh[0] = a; sh[1] = c; }
    }
    __syncthreads();
    float mean = sh[0] * (1.f / DDIM);
    float var  = sh[1] * (1.f / DDIM) - mean * mean;
    float rstd = rsqrtf(fmaxf(var, 0.f) + 1e-5f);
    q[tid]       = (v0 - mean) * rstd * g[tid]       + be[tid];
    q[tid + 256] = (v1 - mean) * rstd * g[tid + 256] + be[tid + 256];
    q[tid + 512] = (v2 - mean) * rstd * g[tid + 512] + be[tid + 512];
}

// ---------------------------------------------------------------------------
// Launch
// ---------------------------------------------------------------------------
extern "C" void kernel_launch(void* const* d_in, const int* in_sizes, int n_in,
                              void* d_out, int out_size)
{
    const float* x_embed = (const float*)d_in[0];
    const float* prompt  = (const float*)d_in[1];
    const float* w1a  = (const float*)d_in[2];
    const float* b1a  = (const float*)d_in[3];
    const float* g1a  = (const float*)d_in[4];
    const float* be1a = (const float*)d_in[5];
    const float* w1b  = (const float*)d_in[6];
    const float* b1b  = (const float*)d_in[7];
    const float* g1b  = (const float*)d_in[8];
    const float* be1b = (const float*)d_in[9];
    const float* w2a  = (const float*)d_in[10];
    const float* b2a  = (const float*)d_in[11];
    const float* g2a  = (const float*)d_in[12];
    const float* be2a = (const float*)d_in[13];
    const float* w2b  = (const float*)d_in[14];
    const float* b2b  = (const float*)d_in[15];
    const float* g2b  = (const float*)d_in[16];
    const float* be2b = (const float*)d_in[17];
    float* out = (float*)d_out;

    int write_aux = (out_size >= OUT_TOTAL) ? 1 : 0;

    float* bufB = nullptr;
    uint4 *A16, *Wa16, *Wb16;
    cudaGetSymbolAddress((void**)&bufB, g_bufB);
    cudaGetSymbolAddress((void**)&A16,  g_A16);
    cudaGetSymbolAddress((void**)&Wa16, g_Wa16);
    cudaGetSymbolAddress((void**)&Wb16, g_Wb16);

    // prompt selection pipeline
    pnorm_kernel<<<POOLN, 256>>>(prompt);
    xmean_norm_kernel<<<BDIM, 256>>>(x_embed);
    sim_topk_kernel<<<BDIM, 256>>>(out, write_aux);
    if (write_aux) reduce_rsim_kernel<<<1, 256>>>(out);

    // weight transpose -> fp16
    wprep_kernel<<<dim3(24, 24), dim3(32, 8)>>>(w2a, (uint32_t*)Wa16);
    wprep_kernel<<<dim3(24, 24), dim3(32, 8)>>>(w2b, (uint32_t*)Wb16);

    // fused mlp_1 -> fp16 activations
    int mlp1_smem = 17088 * (int)sizeof(float);
    cudaFuncSetAttribute(mlp1_fused_kernel,
                         cudaFuncAttributeMaxDynamicSharedMemorySize, mlp1_smem);
    mlp1_fused_kernel<<<dim3(DDIM / 64, BDIM), 256, mlp1_smem>>>(
        x_embed, prompt, w1a, b1a, g1a, be1a, w1b, b1b, g1b, be1b);

    // mlp_2: fp16 mma GEMM + LN stages
    cudaFuncSetAttribute(gemm_f16_kernel,
                         cudaFuncAttributeMaxDynamicSharedMemorySize, GEMM_SMEM);
    dim3 ggrid(DDIM / 128, MROWS / 128);   // (6, 512)
    gemm_f16_kernel<<<ggrid, 256, GEMM_SMEM>>>(A16, Wa16, b2a, bufB);
    ln_rows_f16_kernel<<<MROWS, 256>>>(bufB, (uint32_t*)A16, g2a, be2a);
    gemm_f16_kernel<<<ggrid, 256, GEMM_SMEM>>>(A16, Wb16, b2b, bufB);
    ln_rows_kernel<<<MROWS, 256>>>(bufB, out, g2b, be2b);
}